// round 3
// baseline (speedup 1.0000x reference)
#include <cuda_runtime.h>
#include <math.h>

#define NW 14
#define NL 4
#define NSTATE (1 << NW)
#define THREADS 1024
#define AMPS 16
#define PI_F 3.14159265358979323846f

typedef unsigned long long u64;

// ---------- packed f32x2 helpers ----------
__device__ __forceinline__ u64 pk(float lo, float hi) {
    u64 r; asm("mov.b64 %0, {%1, %2};" : "=l"(r) : "f"(lo), "f"(hi)); return r;
}
__device__ __forceinline__ void unpk(u64 a, float& lo, float& hi) {
    asm("mov.b64 {%0, %1}, %2;" : "=f"(lo), "=f"(hi) : "l"(a));
}
__device__ __forceinline__ u64 swp(u64 a) {
    float lo, hi; unpk(a, lo, hi);
    u64 r; asm("mov.b64 %0, {%1, %2};" : "=l"(r) : "f"(hi), "f"(lo)); return r;
}
__device__ __forceinline__ u64 ffma2_(u64 a, u64 b, u64 c) {
    u64 d; asm("fma.rn.f32x2 %0, %1, %2, %3;" : "=l"(d) : "l"(a), "l"(b), "l"(c));
    return d;
}
__device__ __forceinline__ u64 fmul2_(u64 a, u64 b) {
    u64 d; asm("mul.rn.f32x2 %0, %1, %2;" : "=l"(d) : "l"(a), "l"(b));
    return d;
}

__device__ __forceinline__ float2 cmul(float2 a, float2 b) {
    return make_float2(a.x * b.x - a.y * b.y, a.x * b.y + a.y * b.x);
}
__device__ __forceinline__ float2 cadd(float2 a, float2 b) {
    return make_float2(a.x + b.x, a.y + b.y);
}

// XOR swizzle: u64-bank = low 4 bits; XOR with bits 4-7 -> conflict-free
// per half-warp for every access pattern used below.
__device__ __forceinline__ int sw(int i) { return i ^ ((i >> 4) & 15); }

// Packed complex 2x2 gate on local bit L of r[16].
// g: {B00,P00,B01,P01,B10,P10,B11,P11}; B=(re,re), P=(-im,+im).
template <int L>
__device__ __forceinline__ void apply_gate(u64* r, const u64* __restrict__ g) {
    const u64 B00 = g[0], P00 = g[1], B01 = g[2], P01 = g[3];
    const u64 B10 = g[4], P10 = g[5], B11 = g[6], P11 = g[7];
#pragma unroll
    for (int p = 0; p < 8; p++) {
        const int lm = (1 << L) - 1;
        const int j0 = ((p & ~lm) << 1) | (p & lm);
        const int j1 = j0 | (1 << L);
        u64 x0 = r[j0], x1 = r[j1];
        u64 x0s = swp(x0), x1s = swp(x1);
        r[j0] = ffma2_(B00, x0, ffma2_(P00, x0s, ffma2_(B01, x1, fmul2_(P01, x1s))));
        r[j1] = ffma2_(B10, x0, ffma2_(P10, x0s, ffma2_(B11, x1, fmul2_(P11, x1s))));
    }
}

// CNOT chain CNOT(0,1)..CNOT(12,13),CNOT(13,0) as a basis permutation.
// Index bit k = wire (13-k). dst_k = xor(src bits k..13) for k<=12;
// dst_13 = xor(src bits 0..12).
__device__ __forceinline__ unsigned cnot_perm(unsigned i) {
    unsigned s = i;
    s ^= s >> 1; s ^= s >> 2; s ^= s >> 4; s ^= s >> 8;
    return (s & 0x1FFFu) | (((s ^ (i >> 13)) & 1u) << 13);
}

__global__ __launch_bounds__(THREADS, 1)
void vqc_kernel(const float* __restrict__ x_raw,
                const float* __restrict__ angles,
                float* __restrict__ out) {
    extern __shared__ unsigned char smem[];
    u64*    sv   = (u64*)smem;                  // [NSTATE] packed (re,im)
    u64*    sU   = sv + NSTATE;                 // [NL*NW*8] packed gate consts
    float2* senc = (float2*)(sU + NL * NW * 8); // [NW] (cos,sin) enc factors
    float*  sred = (float*)(senc + NW);         // [32] reduction scratch

    const int t = threadIdx.x;
    const int b = blockIdx.x;

    // ---- encoding factors ----
    if (t < NW) {
        float th = tanhf(x_raw[b * NW + t]) * PI_F;
        senc[t] = make_float2(cosf(0.5f * th), sinf(0.5f * th));
    }
    // ---- fused U = RZ*RY*RX per (layer,wire) as packed constants ----
    if (t < NL * NW) {
        const int k = t / NW, w = t % NW;
        const float a0 = angles[(k * NW + w) * 3 + 0];
        const float a1 = angles[(k * NW + w) * 3 + 1];
        const float a2 = angles[(k * NW + w) * 3 + 2];
        const float c0 = cosf(0.5f * a0), s0 = sinf(0.5f * a0);
        const float c1 = cosf(0.5f * a1), s1 = sinf(0.5f * a1);
        const float2 rx00 = make_float2(c0, 0.f),  rx01 = make_float2(0.f, -s0);
        const float2 rx10 = make_float2(0.f, -s0), rx11 = make_float2(c0, 0.f);
        const float2 ry00 = make_float2(c1, 0.f),  ry01 = make_float2(-s1, 0.f);
        const float2 ry10 = make_float2(s1, 0.f),  ry11 = make_float2(c1, 0.f);
        float2 m00 = cadd(cmul(ry00, rx00), cmul(ry01, rx10));
        float2 m01 = cadd(cmul(ry00, rx01), cmul(ry01, rx11));
        float2 m10 = cadd(cmul(ry10, rx00), cmul(ry11, rx10));
        float2 m11 = cadd(cmul(ry10, rx01), cmul(ry11, rx11));
        const float2 em = make_float2(cosf(0.5f * a2), -sinf(0.5f * a2));
        const float2 ep = make_float2(em.x, -em.y);
        float2 u00 = cmul(em, m00), u01 = cmul(em, m01);
        float2 u10 = cmul(ep, m10), u11 = cmul(ep, m11);
        u64* g = sU + t * 8;
        g[0] = pk(u00.x, u00.x); g[1] = pk(-u00.y, u00.y);
        g[2] = pk(u01.x, u01.x); g[3] = pk(-u01.y, u01.y);
        g[4] = pk(u10.x, u10.x); g[5] = pk(-u10.y, u10.y);
        g[6] = pk(u11.x, u11.x); g[7] = pk(-u11.y, u11.y);
    }
    __syncthreads();

    u64 r[AMPS];

    for (int k = 0; k < NL; k++) {
        const u64* Gk = sU + k * NW * 8;

        // ===== Pass A: i = (t<<4)|j. Local bits 0-3 = wires 13,12,11,10 =====
        if (k == 0) {
            // RY-encoded product state built in registers.
            // wire w<=9 is t bit (9-w); wires 10..13 are j bits 3..0.
            float v[AMPS];
            float common = 1.f;
#pragma unroll
            for (int w = 0; w < 10; w++) {
                float2 cs = senc[w];
                common *= ((t >> (9 - w)) & 1) ? cs.y : cs.x;
            }
            v[0] = common;
#pragma unroll
            for (int st = 0; st < 4; st++) {
                float2 cs = senc[10 + st];
#pragma unroll
                for (int kk = (1 << st) - 1; kk >= 0; kk--) {
                    float vv = v[kk];
                    v[2 * kk + 1] = vv * cs.y;
                    v[2 * kk]     = vv * cs.x;
                }
            }
#pragma unroll
            for (int j = 0; j < AMPS; j++) r[j] = pk(v[j], 0.f);
        } else {
#pragma unroll
            for (int j = 0; j < AMPS; j++) r[j] = sv[sw((t << 4) | j)];
        }
        apply_gate<0>(r, Gk + 13 * 8);
        apply_gate<1>(r, Gk + 12 * 8);
        apply_gate<2>(r, Gk + 11 * 8);
        apply_gate<3>(r, Gk + 10 * 8);
#pragma unroll
        for (int j = 0; j < AMPS; j++) sv[sw((t << 4) | j)] = r[j];
        __syncthreads();

        // ===== Pass B: i = ((t>>4)<<8)|(j<<4)|(t&15). bits 4-7 = wires 9,8,7,6
        {
            const int hi = (t >> 4) << 8, lo = t & 15;
#pragma unroll
            for (int j = 0; j < AMPS; j++) r[j] = sv[sw(hi | (j << 4) | lo)];
            apply_gate<0>(r, Gk + 9 * 8);
            apply_gate<1>(r, Gk + 8 * 8);
            apply_gate<2>(r, Gk + 7 * 8);
            apply_gate<3>(r, Gk + 6 * 8);
#pragma unroll
            for (int j = 0; j < AMPS; j++) sv[sw(hi | (j << 4) | lo)] = r[j];
        }
        __syncthreads();

        // ===== Pass C: i = ((t>>8)<<12)|(j<<8)|(t&255). bits 8-11 = wires 5,4,3,2
        {
            const int hi = (t >> 8) << 12, lo = t & 255;
#pragma unroll
            for (int j = 0; j < AMPS; j++) r[j] = sv[sw(hi | (j << 8) | lo)];
            apply_gate<0>(r, Gk + 5 * 8);
            apply_gate<1>(r, Gk + 4 * 8);
            apply_gate<2>(r, Gk + 3 * 8);
            apply_gate<3>(r, Gk + 2 * 8);
#pragma unroll
            for (int j = 0; j < AMPS; j++) sv[sw(hi | (j << 8) | lo)] = r[j];
        }
        __syncthreads();

        // ===== Pass D: i = (j<<10)|t. Local bits 2,3 (= bits 12,13) = wires 1,0
#pragma unroll
        for (int j = 0; j < AMPS; j++) r[j] = sv[sw((j << 10) | t)];
        apply_gate<2>(r, Gk + 1 * 8);
        apply_gate<3>(r, Gk + 0 * 8);

        if (k < NL - 1) {
            // Fuse the CNOT-chain permutation into the store.
#pragma unroll
            for (int j = 0; j < AMPS; j++) {
                unsigned i = (unsigned)((j << 10) | t);
                sv[sw((int)cnot_perm(i))] = r[j];
            }
            __syncthreads();
        } else {
            // <Z0>: sign = final bit13 = parity(src bits 0..12).
            float acc = 0.f;
#pragma unroll
            for (int j = 0; j < AMPS; j++) {
                int i = (j << 10) | t;
                float re, im; unpk(r[j], re, im);
                float vv = fmaf(re, re, im * im);
                acc += (__popc(i & 0x1FFF) & 1) ? -vv : vv;
            }
#pragma unroll
            for (int off = 16; off; off >>= 1)
                acc += __shfl_xor_sync(0xffffffffu, acc, off);
            if ((t & 31) == 0) sred[t >> 5] = acc;
            __syncthreads();
            if (t < 32) {
                float v = sred[t];
#pragma unroll
                for (int off = 16; off; off >>= 1)
                    v += __shfl_xor_sync(0xffffffffu, v, off);
                if (t == 0) out[b] = v;
            }
        }
    }
}

extern "C" void kernel_launch(void* const* d_in, const int* in_sizes, int n_in,
                              void* d_out, int out_size) {
    const float* x   = (const float*)d_in[0];
    const float* ang = (const float*)d_in[1];
    if (n_in >= 2 && in_sizes[0] == NL * NW * 3 && in_sizes[1] != NL * NW * 3) {
        const float* tmp = x; x = ang; ang = tmp;
    }
    float* out = (float*)d_out;

    const int smem_bytes = NSTATE * 8 + NL * NW * 8 * 8 + NW * 8 + 32 * 4;
    cudaFuncSetAttribute(vqc_kernel, cudaFuncAttributeMaxDynamicSharedMemorySize,
                         smem_bytes);
    vqc_kernel<<<1024, THREADS, smem_bytes>>>(x, ang, out);
}

// round 4
// speedup vs baseline: 1.2650x; 1.2650x over previous
#include <cuda_runtime.h>
#include <math.h>

#define NW 14
#define NL 4
#define NSTATE (1 << NW)
#define THREADS 512
#define PI_F 3.14159265358979323846f

typedef unsigned long long u64;

// ---------- packed f32x2 helpers (FFMA2 path) ----------
__device__ __forceinline__ u64 pk(float lo, float hi) {
    u64 r; asm("mov.b64 %0, {%1, %2};" : "=l"(r) : "f"(lo), "f"(hi)); return r;
}
__device__ __forceinline__ void unpk(u64 a, float& lo, float& hi) {
    asm("mov.b64 {%0, %1}, %2;" : "=f"(lo), "=f"(hi) : "l"(a));
}
__device__ __forceinline__ u64 swp(u64 a) {
    float lo, hi; unpk(a, lo, hi);
    u64 r; asm("mov.b64 %0, {%1, %2};" : "=l"(r) : "f"(hi), "f"(lo)); return r;
}
__device__ __forceinline__ u64 ffma2_(u64 a, u64 b, u64 c) {
    u64 d; asm("fma.rn.f32x2 %0, %1, %2, %3;" : "=l"(d) : "l"(a), "l"(b), "l"(c));
    return d;
}
__device__ __forceinline__ u64 fmul2_(u64 a, u64 b) {
    u64 d; asm("mul.rn.f32x2 %0, %1, %2;" : "=l"(d) : "l"(a), "l"(b));
    return d;
}

__device__ __forceinline__ float2 cmul(float2 a, float2 b) {
    return make_float2(a.x * b.x - a.y * b.y, a.x * b.y + a.y * b.x);
}
__device__ __forceinline__ float2 cadd(float2 a, float2 b) {
    return make_float2(a.x + b.x, a.y + b.y);
}

// Swizzle: u64-slot bank = low 4 bits; XOR with bits 5-8 keeps every access
// pattern below (incl. the CNOT scatter) conflict-free per 16-lane phase.
__device__ __forceinline__ int swz(int a) { return a ^ ((a >> 5) & 15); }

// Register butterfly: 2x2 complex gate on local bit L of r[32].
// g: {B00,P00,B01,P01,B10,P10,B11,P11}; B=(re,re), P=(-im,+im).
template <int L>
__device__ __forceinline__ void apply_gate(u64* r, const u64* __restrict__ g) {
    const u64 B00 = g[0], P00 = g[1], B01 = g[2], P01 = g[3];
    const u64 B10 = g[4], P10 = g[5], B11 = g[6], P11 = g[7];
#pragma unroll
    for (int p = 0; p < 16; p++) {
        const int lm = (1 << L) - 1;
        const int j0 = ((p & ~lm) << 1) | (p & lm);
        const int j1 = j0 | (1 << L);
        u64 x0 = r[j0], x1 = r[j1];
        u64 x0s = swp(x0), x1s = swp(x1);
        r[j0] = ffma2_(B00, x0, ffma2_(P00, x0s, ffma2_(B01, x1, fmul2_(P01, x1s))));
        r[j1] = ffma2_(B10, x0, ffma2_(P10, x0s, ffma2_(B11, x1, fmul2_(P11, x1s))));
    }
}

// Distributed butterfly on lane bit L (index bit 5+L): partner via shfl_xor.
// Each thread computes only its own half: y = U[m][m]*x + U[m][1-m]*x_partner.
template <int L>
__device__ __forceinline__ void apply_gate_shfl(u64* r, const u64* __restrict__ g,
                                                int lane) {
    const int m = (lane >> L) & 1;
    const u64 Bs = m ? g[6] : g[0];
    const u64 Ps = m ? g[7] : g[1];
    const u64 Bo = m ? g[4] : g[2];
    const u64 Po = m ? g[5] : g[3];
#pragma unroll
    for (int j = 0; j < 32; j++) {
        u64 x  = r[j];
        u64 xo = __shfl_xor_sync(0xffffffffu, x, 1 << L);
        r[j] = ffma2_(Bs, x, ffma2_(Ps, swp(x), ffma2_(Bo, xo, fmul2_(Po, swp(xo)))));
    }
}

// CNOT chain CNOT(0,1)..CNOT(12,13),CNOT(13,0) as a basis permutation.
// Index bit k = wire (13-k). dst_k = xor(src k..13) for k<=12;
// dst_13 = xor(src 0..12).
__device__ __forceinline__ unsigned cnot_perm(unsigned i) {
    unsigned s = i;
    s ^= s >> 1; s ^= s >> 2; s ^= s >> 4; s ^= s >> 8;
    return (s & 0x1FFFu) | (((s ^ (i >> 13)) & 1u) << 13);
}

__global__ __launch_bounds__(THREADS, 1)
void vqc_kernel(const float* __restrict__ x_raw,
                const float* __restrict__ angles,
                float* __restrict__ out) {
    extern __shared__ unsigned char smem[];
    u64*    sv   = (u64*)smem;                  // [NSTATE] packed (re,im)
    u64*    sU   = sv + NSTATE;                 // [NL*NW*8] packed gate consts
    float2* senc = (float2*)(sU + NL * NW * 8); // [NW] (cos,sin) enc factors
    float*  sred = (float*)(senc + NW);         // [16] reduction scratch

    const int t    = threadIdx.x;
    const int lane = t & 31;
    const int w    = t >> 5;          // warp id: index bits 10-13
    const int b    = blockIdx.x;

    // ---- encoding factors ----
    if (t < NW) {
        float th = tanhf(x_raw[b * NW + t]) * PI_F;
        senc[t] = make_float2(cosf(0.5f * th), sinf(0.5f * th));
    }
    // ---- fused U = RZ*RY*RX per (layer,wire), packed constants ----
    if (t < NL * NW) {
        const int k = t / NW, wi = t % NW;
        const float a0 = angles[(k * NW + wi) * 3 + 0];
        const float a1 = angles[(k * NW + wi) * 3 + 1];
        const float a2 = angles[(k * NW + wi) * 3 + 2];
        const float c0 = cosf(0.5f * a0), s0 = sinf(0.5f * a0);
        const float c1 = cosf(0.5f * a1), s1 = sinf(0.5f * a1);
        const float2 rx00 = make_float2(c0, 0.f),  rx01 = make_float2(0.f, -s0);
        const float2 rx10 = make_float2(0.f, -s0), rx11 = make_float2(c0, 0.f);
        const float2 ry00 = make_float2(c1, 0.f),  ry01 = make_float2(-s1, 0.f);
        const float2 ry10 = make_float2(s1, 0.f),  ry11 = make_float2(c1, 0.f);
        float2 m00 = cadd(cmul(ry00, rx00), cmul(ry01, rx10));
        float2 m01 = cadd(cmul(ry00, rx01), cmul(ry01, rx11));
        float2 m10 = cadd(cmul(ry10, rx00), cmul(ry11, rx10));
        float2 m11 = cadd(cmul(ry10, rx01), cmul(ry11, rx11));
        const float2 em = make_float2(cosf(0.5f * a2), -sinf(0.5f * a2));
        const float2 ep = make_float2(em.x, -em.y);
        float2 u00 = cmul(em, m00), u01 = cmul(em, m01);
        float2 u10 = cmul(ep, m10), u11 = cmul(ep, m11);
        u64* g = sU + t * 8;
        g[0] = pk(u00.x, u00.x); g[1] = pk(-u00.y, u00.y);
        g[2] = pk(u01.x, u01.x); g[3] = pk(-u01.y, u01.y);
        g[4] = pk(u10.x, u10.x); g[5] = pk(-u10.y, u10.y);
        g[6] = pk(u11.x, u11.x); g[7] = pk(-u11.y, u11.y);
    }
    __syncthreads();

    u64 r[32];

    for (int k = 0; k < NL; k++) {
        const u64* Gk = sU + k * NW * 8;

        // ===== P1: amps i = (w<<10)|(lane<<5)|j.  reg bits j = wires 9..13,
        //           lane bits = wires 4..8 =====
        if (k == 0) {
            // RY-encoded product state built in registers.
            // wire W<=8 is t bit (8-W); reg bit b = wire (13-b).
            float v[32];
            float common = 1.f;
#pragma unroll
            for (int W = 0; W < 9; W++) {
                float2 cs = senc[W];
                common *= ((t >> (8 - W)) & 1) ? cs.y : cs.x;
            }
            v[0] = common;
#pragma unroll
            for (int st = 0; st < 5; st++) {   // stage st -> wire 9+st -> j bit (4-st)
                float2 cs = senc[9 + st];
#pragma unroll
                for (int kk = (1 << st) - 1; kk >= 0; kk--) {
                    float vv = v[kk];
                    v[2 * kk + 1] = vv * cs.y;
                    v[2 * kk]     = vv * cs.x;
                }
            }
#pragma unroll
            for (int j = 0; j < 32; j++) r[j] = pk(v[j], 0.f);
        } else {
            const int base = (w << 10) | (lane << 5);
#pragma unroll
            for (int j = 0; j < 32; j++) r[j] = sv[swz(base | j)];
        }
        // register gates on wires 13..9 (local bits 0..4); LSB-first so compute
        // overlaps the load stream
        apply_gate<0>(r, Gk + 13 * 8);
        apply_gate<1>(r, Gk + 12 * 8);
        apply_gate<2>(r, Gk + 11 * 8);
        apply_gate<3>(r, Gk + 10 * 8);
        apply_gate<4>(r, Gk + 9 * 8);
        // shuffle gates on wires 8..4 (lane bits 0..4) — no SMEM, no barrier
        apply_gate_shfl<0>(r, Gk + 8 * 8, lane);
        apply_gate_shfl<1>(r, Gk + 7 * 8, lane);
        apply_gate_shfl<2>(r, Gk + 6 * 8, lane);
        apply_gate_shfl<3>(r, Gk + 5 * 8, lane);
        apply_gate_shfl<4>(r, Gk + 4 * 8, lane);
        // store with b0-4 <-> b5-9 swapped: amp i -> addr (i10-13, i0-4, i5-9)
        {
            const int hw = w << 10;
#pragma unroll
            for (int j = 0; j < 32; j++) sv[swz(hw | (j << 5) | lane)] = r[j];
        }
        __syncthreads();

        // ===== P2: load with b10-13 in local bits 0-3 =====
        // addr a = (j4<<10)|(e<<9)|(w<<5)|lane holds amp
        //   i = (j4<<10)|(lane<<5)|(e<<4)|w
#pragma unroll
        for (int j2 = 0; j2 < 32; j2++) {
            const int j4 = j2 & 15, e = j2 >> 4;
            r[j2] = sv[swz((j4 << 10) | (e << 9) | (w << 5) | lane)];
        }
        // gates on wires 3..0 (local bits 0..3); local bit 4 (e) inert
        apply_gate<0>(r, Gk + 3 * 8);
        apply_gate<1>(r, Gk + 2 * 8);
        apply_gate<2>(r, Gk + 1 * 8);
        apply_gate<3>(r, Gk + 0 * 8);

        if (k < NL - 1) {
            // CNOT-chain permutation fused into the store (back to P1 layout).
#pragma unroll
            for (int j2 = 0; j2 < 32; j2++) {
                const int j4 = j2 & 15, e = j2 >> 4;
                unsigned i = (unsigned)((j4 << 10) | (lane << 5) | (e << 4) | w);
                sv[swz((int)cnot_perm(i))] = r[j2];
            }
            __syncthreads();
        } else {
            // <Z0>: sign = final bit13 after CNOTs = parity(src bits 0..12).
            float acc = 0.f;
#pragma unroll
            for (int j2 = 0; j2 < 32; j2++) {
                const int j4 = j2 & 15, e = j2 >> 4;
                const int i = (j4 << 10) | (lane << 5) | (e << 4) | w;
                float re, im; unpk(r[j2], re, im);
                float vv = fmaf(re, re, im * im);
                acc += (__popc(i & 0x1FFF) & 1) ? -vv : vv;
            }
#pragma unroll
            for (int off = 16; off; off >>= 1)
                acc += __shfl_xor_sync(0xffffffffu, acc, off);
            if (lane == 0) sred[w] = acc;
            __syncthreads();
            if (t < 32) {
                float v = (t < 16) ? sred[t] : 0.f;
#pragma unroll
                for (int off = 8; off; off >>= 1)
                    v += __shfl_xor_sync(0xffffffffu, v, off);
                if (t == 0) out[b] = v;
            }
        }
    }
}

extern "C" void kernel_launch(void* const* d_in, const int* in_sizes, int n_in,
                              void* d_out, int out_size) {
    const float* x   = (const float*)d_in[0];
    const float* ang = (const float*)d_in[1];
    if (n_in >= 2 && in_sizes[0] == NL * NW * 3 && in_sizes[1] != NL * NW * 3) {
        const float* tmp = x; x = ang; ang = tmp;
    }
    float* out = (float*)d_out;

    const int smem_bytes = NSTATE * 8 + NL * NW * 8 * 8 + NW * 8 + 16 * 4;
    cudaFuncSetAttribute(vqc_kernel, cudaFuncAttributeMaxDynamicSharedMemorySize,
                         smem_bytes);
    vqc_kernel<<<1024, THREADS, smem_bytes>>>(x, ang, out);
}

// round 5
// speedup vs baseline: 1.3951x; 1.1029x over previous
#include <cuda_runtime.h>
#include <math.h>

#define NW 14
#define NL 4
#define NSTATE (1 << NW)
#define THREADS 512
#define PI_F 3.14159265358979323846f

typedef unsigned long long u64;

// ---------- packed f32x2 helpers (sm_103a FFMA2 path) ----------
__device__ __forceinline__ u64 pk(float lo, float hi) {
    u64 r; asm("mov.b64 %0, {%1, %2};" : "=l"(r) : "f"(lo), "f"(hi)); return r;
}
__device__ __forceinline__ void unpk(u64 a, float& lo, float& hi) {
    asm("mov.b64 {%0, %1}, %2;" : "=f"(lo), "=f"(hi) : "l"(a));
}
__device__ __forceinline__ u64 swp(u64 a) {
    float lo, hi; unpk(a, lo, hi);
    u64 r; asm("mov.b64 %0, {%1, %2};" : "=l"(r) : "f"(hi), "f"(lo)); return r;
}
__device__ __forceinline__ u64 ffma2_(u64 a, u64 b, u64 c) {
    u64 d; asm("fma.rn.f32x2 %0, %1, %2, %3;" : "=l"(d) : "l"(a), "l"(b), "l"(c));
    return d;
}
__device__ __forceinline__ u64 fmul2_(u64 a, u64 b) {
    u64 d; asm("mul.rn.f32x2 %0, %1, %2;" : "=l"(d) : "l"(a), "l"(b));
    return d;
}

__device__ __forceinline__ float2 cmul(float2 a, float2 b) {
    return make_float2(a.x * b.x - a.y * b.y, a.x * b.y + a.y * b.x);
}
__device__ __forceinline__ float2 cadd(float2 a, float2 b) {
    return make_float2(a.x + b.x, a.y + b.y);
}

// Packed complex 2x2 gate on local bit L of register block r[32].
// Gate g: 8 packed constants {B00,P00,B01,P01,B10,P10,B11,P11},
//   B = (u.re, u.re), P = (-u.im, +u.im).
// y = B*X + P*swap(X) implements complex multiply in 2 packed ops.
template <int L>
__device__ __forceinline__ void apply_gate(u64* r, const u64* __restrict__ g) {
    const u64 B00 = g[0], P00 = g[1], B01 = g[2], P01 = g[3];
    const u64 B10 = g[4], P10 = g[5], B11 = g[6], P11 = g[7];
#pragma unroll
    for (int p = 0; p < 16; p++) {
        const int lm = (1 << L) - 1;
        const int j0 = ((p & ~lm) << 1) | (p & lm);
        const int j1 = j0 | (1 << L);
        u64 x0 = r[j0], x1 = r[j1];
        u64 x0s = swp(x0), x1s = swp(x1);
        r[j0] = ffma2_(B00, x0, ffma2_(P00, x0s, ffma2_(B01, x1, fmul2_(P01, x1s))));
        r[j1] = ffma2_(B10, x0, ffma2_(P10, x0s, ffma2_(B11, x1, fmul2_(P11, x1s))));
    }
}

// CNOT chain CNOT(0,1)..CNOT(12,13),CNOT(13,0) as basis permutation.
// Index bit k = wire (13-k). dst_k = xor(src bits k..13) for k<=12;
// dst_13 = xor(src bits 0..12).
__device__ __forceinline__ unsigned cnot_perm(unsigned i) {
    unsigned s = i;
    s ^= s >> 1; s ^= s >> 2; s ^= s >> 4; s ^= s >> 8;
    return (s & 0x1FFFu) | (((s ^ (i >> 13)) & 1u) << 13);
}

// Swizzle used by the scatter store (matches pass A's amp->slot layout):
// slot(i) = i with low-5 XORed by bits 5-9 (the inverse of pass A's read map).
__device__ __forceinline__ int sw(int i) { return i ^ ((i >> 5) & 31); }

__global__ __launch_bounds__(THREADS, 1)
void vqc_kernel(const float* __restrict__ x_raw,
                const float* __restrict__ angles,
                float* __restrict__ out) {
    extern __shared__ unsigned char smem[];
    u64*    sv   = (u64*)smem;                 // [NSTATE] statevector (re,im packed)
    u64*    sU   = sv + NSTATE;                // [NL*NW*8] packed gate constants
    float2* senc = (float2*)(sU + NL * NW * 8);// [NW] (cos,sin) encoding factors
    float*  sred = (float*)(senc + NW);        // [16] reduction scratch

    const int tid = threadIdx.x;
    const int b   = blockIdx.x;

    // ---- encoding factors ----
    if (tid < NW) {
        float t = tanhf(x_raw[b * NW + tid]) * PI_F;
        senc[tid] = make_float2(cosf(0.5f * t), sinf(0.5f * t));
    }
    // ---- fused U = RZ*RY*RX per (layer,wire), stored as packed constants ----
    if (tid < NL * NW) {
        const int k = tid / NW, w = tid % NW;
        const float a0 = angles[(k * NW + w) * 3 + 0];
        const float a1 = angles[(k * NW + w) * 3 + 1];
        const float a2 = angles[(k * NW + w) * 3 + 2];
        const float c0 = cosf(0.5f * a0), s0 = sinf(0.5f * a0);
        const float c1 = cosf(0.5f * a1), s1 = sinf(0.5f * a1);
        const float2 rx00 = make_float2(c0, 0.f),  rx01 = make_float2(0.f, -s0);
        const float2 rx10 = make_float2(0.f, -s0), rx11 = make_float2(c0, 0.f);
        const float2 ry00 = make_float2(c1, 0.f),  ry01 = make_float2(-s1, 0.f);
        const float2 ry10 = make_float2(s1, 0.f),  ry11 = make_float2(c1, 0.f);
        float2 m00 = cadd(cmul(ry00, rx00), cmul(ry01, rx10));
        float2 m01 = cadd(cmul(ry00, rx01), cmul(ry01, rx11));
        float2 m10 = cadd(cmul(ry10, rx00), cmul(ry11, rx10));
        float2 m11 = cadd(cmul(ry10, rx01), cmul(ry11, rx11));
        const float2 em = make_float2(cosf(0.5f * a2), -sinf(0.5f * a2));
        const float2 ep = make_float2(em.x, -em.y);
        float2 u00 = cmul(em, m00), u01 = cmul(em, m01);
        float2 u10 = cmul(ep, m10), u11 = cmul(ep, m11);
        u64* g = sU + tid * 8;
        g[0] = pk(u00.x, u00.x); g[1] = pk(-u00.y, u00.y);
        g[2] = pk(u01.x, u01.x); g[3] = pk(-u01.y, u01.y);
        g[4] = pk(u10.x, u10.x); g[5] = pk(-u10.y, u10.y);
        g[6] = pk(u11.x, u11.x); g[7] = pk(-u11.y, u11.y);
    }
    __syncthreads();

    u64 r[32];

    for (int k = 0; k < NL; k++) {
        const u64* Gk = sU + k * NW * 8;

        // ===== Pass A: i = tid*32 + j, wires 9..13 (j bits 4..0) =====
        // Pass A's region [1024w, 1024w+1024) is warp-private; so is pass B's.
        if (k == 0) {
            // RY-encoded product state built directly in registers.
            float v[32];
            float common = 1.f;
#pragma unroll
            for (int w = 0; w < 9; w++) {
                float2 cs = senc[w];
                common *= ((tid >> (8 - w)) & 1) ? cs.y : cs.x;
            }
            v[0] = common;
#pragma unroll
            for (int st = 0; st < 5; st++) {
                float2 cs = senc[9 + st];
#pragma unroll
                for (int kk = (1 << st) - 1; kk >= 0; kk--) {
                    float t = v[kk];
                    v[2 * kk + 1] = t * cs.y;
                    v[2 * kk]     = t * cs.x;
                }
            }
#pragma unroll
            for (int j = 0; j < 32; j++) r[j] = pk(v[j], 0.f);
        } else {
            const int m = tid & 31, base = tid * 32;
#pragma unroll
            for (int j = 0; j < 32; j++) r[j] = sv[base + (j ^ m)];
        }
        apply_gate<4>(r, Gk + 9 * 8);
        apply_gate<3>(r, Gk + 10 * 8);
        apply_gate<2>(r, Gk + 11 * 8);
        apply_gate<1>(r, Gk + 12 * 8);
        apply_gate<0>(r, Gk + 13 * 8);
        {
            const int m = tid & 31, base = tid * 32;
#pragma unroll
            for (int j = 0; j < 32; j++) sv[base + (j ^ m)] = r[j];
        }
        // A-store -> B-load stays within the warp's 1024-slot region:
        // only warp-level ordering is required, not a CTA barrier.
        __syncwarp();

        // ===== Pass B: i = ((tid>>5)<<10)|(j<<5)|(tid&31), wires 4..8 =====
        {
            const int hi = (tid >> 5) << 10, lo = tid & 31;
#pragma unroll
            for (int j = 0; j < 32; j++) r[j] = sv[hi + (j << 5) + (lo ^ j)];
        }
        apply_gate<4>(r, Gk + 4 * 8);
        apply_gate<3>(r, Gk + 5 * 8);
        apply_gate<2>(r, Gk + 6 * 8);
        apply_gate<1>(r, Gk + 7 * 8);
        apply_gate<0>(r, Gk + 8 * 8);
        {
            const int hi = (tid >> 5) << 10, lo = tid & 31;
#pragma unroll
            for (int j = 0; j < 32; j++) sv[hi + (j << 5) + (lo ^ j)] = r[j];
        }
        __syncthreads();   // B-store -> C-load crosses warps

        // ===== Pass C: i = (j<<9) | tid, wires 0..3 (j bits 4..1) =====
        {
            const int mid = (tid >> 5) & 15;
#pragma unroll
            for (int j = 0; j < 32; j++) {
                int sl = (j << 9) | (tid ^ mid ^ ((j & 1) << 4));
                r[j] = sv[sl];
            }
        }
        apply_gate<4>(r, Gk + 0 * 8);
        apply_gate<3>(r, Gk + 1 * 8);
        apply_gate<2>(r, Gk + 2 * 8);
        apply_gate<1>(r, Gk + 3 * 8);

        if (k < NL - 1) {
            // Fuse the CNOT-chain permutation into the store.
#pragma unroll
            for (int j = 0; j < 32; j++) {
                unsigned i = (unsigned)((j << 9) | tid);
                unsigned d = cnot_perm(i);
                sv[sw((int)d)] = r[j];
            }
            __syncthreads();   // scatter -> next-layer A-load crosses warps
        } else {
            // <Z0>: sign = permuted bit13 = parity(src bits 0..12).
            float acc = 0.f;
#pragma unroll
            for (int j = 0; j < 32; j++) {
                int i = (j << 9) | tid;
                float re, im; unpk(r[j], re, im);
                float vv = fmaf(re, re, im * im);
                acc += (__popc(i & 0x1FFF) & 1) ? -vv : vv;
            }
#pragma unroll
            for (int off = 16; off; off >>= 1)
                acc += __shfl_xor_sync(0xffffffffu, acc, off);
            if ((tid & 31) == 0) sred[tid >> 5] = acc;
            __syncthreads();
            if (tid < 32) {
                float v = (tid < 16) ? sred[tid] : 0.f;
#pragma unroll
                for (int off = 8; off; off >>= 1)
                    v += __shfl_xor_sync(0xffffffffu, v, off);
                if (tid == 0) out[b] = v;
            }
        }
    }
}

extern "C" void kernel_launch(void* const* d_in, const int* in_sizes, int n_in,
                              void* d_out, int out_size) {
    const float* x   = (const float*)d_in[0];
    const float* ang = (const float*)d_in[1];
    if (n_in >= 2 && in_sizes[0] == NL * NW * 3 && in_sizes[1] != NL * NW * 3) {
        const float* t = x; x = ang; ang = t;
    }
    float* out = (float*)d_out;

    const int smem_bytes = NSTATE * 8 + NL * NW * 8 * 8 + NW * 8 + 16 * 4;
    cudaFuncSetAttribute(vqc_kernel, cudaFuncAttributeMaxDynamicSharedMemorySize,
                         smem_bytes);
    vqc_kernel<<<1024, THREADS, smem_bytes>>>(x, ang, out);
}

// round 6
// speedup vs baseline: 1.8042x; 1.2932x over previous
#include <cuda_runtime.h>
#include <math.h>

#define NW 14
#define NL 4
#define NSTATE (1 << NW)
#define THREADS 512
#define PI_F 3.14159265358979323846f

typedef unsigned long long u64;

// ---------- packed f32x2 helpers ----------
__device__ __forceinline__ u64 pk(float lo, float hi) {
    u64 r; asm("mov.b64 %0, {%1, %2};" : "=l"(r) : "f"(lo), "f"(hi)); return r;
}
__device__ __forceinline__ void unpk(u64 a, float& lo, float& hi) {
    asm("mov.b64 {%0, %1}, %2;" : "=f"(lo), "=f"(hi) : "l"(a));
}
__device__ __forceinline__ u64 swp(u64 a) {
    float lo, hi; unpk(a, lo, hi);
    u64 r; asm("mov.b64 %0, {%1, %2};" : "=l"(r) : "f"(hi), "f"(lo)); return r;
}
__device__ __forceinline__ u64 ffma2_(u64 a, u64 b, u64 c) {
    u64 d; asm("fma.rn.f32x2 %0, %1, %2, %3;" : "=l"(d) : "l"(a), "l"(b), "l"(c));
    return d;
}
__device__ __forceinline__ u64 fmul2_(u64 a, u64 b) {
    u64 d; asm("mul.rn.f32x2 %0, %1, %2;" : "=l"(d) : "l"(a), "l"(b));
    return d;
}

__device__ __forceinline__ float2 cmul(float2 a, float2 b) {
    return make_float2(a.x * b.x - a.y * b.y, a.x * b.y + a.y * b.x);
}
__device__ __forceinline__ float2 cadd(float2 a, float2 b) {
    return make_float2(a.x + b.x, a.y + b.y);
}

// Real RY butterfly on local bit L: y0 = c*x0 - s*x1, y1 = s*x0 + c*x1.
// 4 packed ops per pair, no swaps.
template <int L>
__device__ __forceinline__ void apply_gateY(u64* r, u64 C2, u64 Sp, u64 Sn) {
#pragma unroll
    for (int p = 0; p < 16; p++) {
        const int lm = (1 << L) - 1;
        const int j0 = ((p & ~lm) << 1) | (p & lm);
        const int j1 = j0 | (1 << L);
        u64 x0 = r[j0], x1 = r[j1];
        r[j0] = ffma2_(Sn, x1, fmul2_(C2, x0));
        r[j1] = ffma2_(Sp, x0, fmul2_(C2, x1));
    }
}

// Per-amp phase multiply: y = z*x, z given as B=(zr,zr), P=(-zi,+zi).
__device__ __forceinline__ u64 dphase(u64 x, u64 B, u64 P) {
    return ffma2_(B, x, fmul2_(P, swp(x)));
}

// CNOT chain CNOT(0,1)..CNOT(12,13),CNOT(13,0) as basis permutation.
// Index bit k = wire (13-k). dst_k = xor(src k..13) for k<=12;
// dst_13 = xor(src 0..12).
__device__ __forceinline__ unsigned cnot_perm(unsigned i) {
    unsigned s = i;
    s ^= s >> 1; s ^= s >> 2; s ^= s >> 4; s ^= s >> 8;
    return (s & 0x1FFFu) | (((s ^ (i >> 13)) & 1u) << 13);
}

// Scatter swizzle (pass-A layout): slot(i) = i with low-5 XORed by bits 5-9.
__device__ __forceinline__ int sw(int i) { return i ^ ((i >> 5) & 31); }

// Gate record layout (stride 8 u64):
// [0]=C2=(c,c) [1]=Sp=(s,s) [2]=Sn=(-s,-s)
// [3]=RB=(zR.re,zR.re) [4]=RP=(-zR.im,zR.im)   zR = e^{i beta}  (D_R)
// [5]=LB=(zL.re,zL.re) [6]=LP=(-zL.im,zL.im)   zL = e^{i alpha} (D_L)
#define GSTRIDE 8

__global__ __launch_bounds__(THREADS, 1)
void vqc_kernel(const float* __restrict__ x_raw,
                const float* __restrict__ angles,
                float* __restrict__ out) {
    extern __shared__ unsigned char smem[];
    u64*    sv   = (u64*)smem;                   // [NSTATE]
    u64*    sU   = sv + NSTATE;                  // [NL*NW*GSTRIDE]
    u64*    sTAB = sU + NL * NW * GSTRIDE;       // [NL*32] D_R low-table B
    u64*    sTAP = sTAB + NL * 32;               // [NL*32] D_R low-table P
    u64*    sTLB = sTAP + NL * 32;               // [NL*32] D_L low-table B
    u64*    sTLP = sTLB + NL * 32;               // [NL*32] D_L low-table P
    float2* senc = (float2*)(sTLP + NL * 32);    // [NW]
    float*  sred = (float*)(senc + NW);          // [16]

    const int tid = threadIdx.x;
    const int b   = blockIdx.x;

    // ---- encoding factors ----
    if (tid < NW) {
        float t = tanhf(x_raw[b * NW + tid]) * PI_F;
        senc[tid] = make_float2(cosf(0.5f * t), sinf(0.5f * t));
    }
    // ---- fused U = RZ*RY*RX per (layer,wire), then ZYZ decomposition ----
    if (tid < NL * NW) {
        const int k = tid / NW, w = tid % NW;
        const float a0 = angles[(k * NW + w) * 3 + 0];
        const float a1 = angles[(k * NW + w) * 3 + 1];
        const float a2 = angles[(k * NW + w) * 3 + 2];
        const float c0 = cosf(0.5f * a0), s0 = sinf(0.5f * a0);
        const float c1 = cosf(0.5f * a1), s1 = sinf(0.5f * a1);
        const float2 rx00 = make_float2(c0, 0.f),  rx01 = make_float2(0.f, -s0);
        const float2 rx10 = make_float2(0.f, -s0), rx11 = make_float2(c0, 0.f);
        const float2 ry00 = make_float2(c1, 0.f),  ry01 = make_float2(-s1, 0.f);
        const float2 ry10 = make_float2(s1, 0.f),  ry11 = make_float2(c1, 0.f);
        float2 m00 = cadd(cmul(ry00, rx00), cmul(ry01, rx10));
        float2 m01 = cadd(cmul(ry00, rx01), cmul(ry01, rx11));
        float2 m10 = cadd(cmul(ry10, rx00), cmul(ry11, rx10));
        float2 m11 = cadd(cmul(ry10, rx01), cmul(ry11, rx11));
        const float2 em = make_float2(cosf(0.5f * a2), -sinf(0.5f * a2));
        const float2 ep = make_float2(em.x, -em.y);
        float2 u00 = cmul(em, m00);
        float2 u10 = cmul(ep, m10);
        // ZYZ: u00 = c*e^{-i(a+b)/2}, u10 = s*e^{i(a-b)/2}
        float c  = sqrtf(u00.x * u00.x + u00.y * u00.y);
        float s  = sqrtf(u10.x * u10.x + u10.y * u10.y);
        float pp = -atan2f(u00.y, u00.x);   // (alpha+beta)/2
        float pm =  atan2f(u10.y, u10.x);   // (alpha-beta)/2
        float al = pp + pm, be = pp - pm;
        float zRr = cosf(be), zRi = sinf(be);
        float zLr = cosf(al), zLi = sinf(al);
        u64* g = sU + tid * GSTRIDE;
        g[0] = pk(c, c); g[1] = pk(s, s); g[2] = pk(-s, -s);
        g[3] = pk(zRr, zRr); g[4] = pk(-zRi, zRi);
        g[5] = pk(zLr, zLr); g[6] = pk(-zLi, zLi);
    }
    __syncthreads();

    // ---- build low-bit diagonal tables ----
    // TA (D_R, pass-A layout): j bit b <-> wire (13-b), factor zR.
    // TL (D_L, pass-C layout): j bit b <-> wire (4-b),  factor zL.
    if (tid < 256) {
        const int k = tid >> 6, isL = (tid >> 5) & 1, j = tid & 31;
        float2 p = make_float2(1.f, 0.f);
#pragma unroll
        for (int bb = 0; bb < 5; bb++) {
            if ((j >> bb) & 1) {
                const int w = isL ? (4 - bb) : (13 - bb);
                const u64* g = sU + (k * NW + w) * GSTRIDE;
                float zr, zd, zi, zt;
                if (isL) { unpk(g[5], zr, zd); unpk(g[6], zt, zi); }
                else     { unpk(g[3], zr, zd); unpk(g[4], zt, zi); }
                p = cmul(p, make_float2(zr, zi));
            }
        }
        if (isL) { sTLB[k * 32 + j] = pk(p.x, p.x); sTLP[k * 32 + j] = pk(-p.y, p.y); }
        else     { sTAB[k * 32 + j] = pk(p.x, p.x); sTAP[k * 32 + j] = pk(-p.y, p.y); }
    }
    __syncthreads();

    u64 r[32];

    for (int k = 0; k < NL; k++) {
        const u64* Gk = sU + k * NW * GSTRIDE;

        // Per-thread high-bit phase for D_R: pass-A hi bits:
        // tid bit m <-> i bit (5+m) <-> wire (8-m), factor zR.
        float2 ptR = make_float2(1.f, 0.f);
#pragma unroll
        for (int m = 0; m < 9; m++) {
            if ((tid >> m) & 1) {
                const u64* g = Gk + (8 - m) * GSTRIDE;
                float zr, zd, zi, zt;
                unpk(g[3], zr, zd); unpk(g[4], zt, zi);
                ptR = cmul(ptR, make_float2(zr, zi));
            }
        }
        const u64 BtR = pk(ptR.x, ptR.x), PtR = pk(-ptR.y, ptR.y);

        // ===== Pass A: i = tid*32 + j, wires 9..13 (j bits 4..0) =====
        if (k == 0) {
            float v[32];
            float common = 1.f;
#pragma unroll
            for (int w = 0; w < 9; w++) {
                float2 cs = senc[w];
                common *= ((tid >> (8 - w)) & 1) ? cs.y : cs.x;
            }
            v[0] = common;
#pragma unroll
            for (int st = 0; st < 5; st++) {
                float2 cs = senc[9 + st];
#pragma unroll
                for (int kk = (1 << st) - 1; kk >= 0; kk--) {
                    float t = v[kk];
                    v[2 * kk + 1] = t * cs.y;
                    v[2 * kk]     = t * cs.x;
                }
            }
#pragma unroll
            for (int j = 0; j < 32; j++) r[j] = pk(v[j], 0.f);
        } else {
            const int m = tid & 31, base = tid * 32;
#pragma unroll
            for (int j = 0; j < 32; j++) r[j] = sv[base + (j ^ m)];
        }
        // D_R (all 14 wires): low-5 table + per-thread hi phase.
#pragma unroll
        for (int j = 0; j < 32; j++)
            r[j] = dphase(dphase(r[j], sTAB[k * 32 + j], sTAP[k * 32 + j]), BtR, PtR);
        // RY butterflies, wires 13..9 on local bits 0..4
        apply_gateY<0>(r, Gk[13 * GSTRIDE], Gk[13 * GSTRIDE + 1], Gk[13 * GSTRIDE + 2]);
        apply_gateY<1>(r, Gk[12 * GSTRIDE], Gk[12 * GSTRIDE + 1], Gk[12 * GSTRIDE + 2]);
        apply_gateY<2>(r, Gk[11 * GSTRIDE], Gk[11 * GSTRIDE + 1], Gk[11 * GSTRIDE + 2]);
        apply_gateY<3>(r, Gk[10 * GSTRIDE], Gk[10 * GSTRIDE + 1], Gk[10 * GSTRIDE + 2]);
        apply_gateY<4>(r, Gk[ 9 * GSTRIDE], Gk[ 9 * GSTRIDE + 1], Gk[ 9 * GSTRIDE + 2]);
        {
            const int m = tid & 31, base = tid * 32;
#pragma unroll
            for (int j = 0; j < 32; j++) sv[base + (j ^ m)] = r[j];
        }
        __syncwarp();   // A-store -> B-load is warp-private

        // ===== Pass B: i = ((tid>>5)<<10)|(j<<5)|(tid&31), wires 4..8 =====
        {
            const int hi = (tid >> 5) << 10, lo = tid & 31;
#pragma unroll
            for (int j = 0; j < 32; j++) r[j] = sv[hi + (j << 5) + (lo ^ j)];
        }
        apply_gateY<0>(r, Gk[8 * GSTRIDE], Gk[8 * GSTRIDE + 1], Gk[8 * GSTRIDE + 2]);
        apply_gateY<1>(r, Gk[7 * GSTRIDE], Gk[7 * GSTRIDE + 1], Gk[7 * GSTRIDE + 2]);
        apply_gateY<2>(r, Gk[6 * GSTRIDE], Gk[6 * GSTRIDE + 1], Gk[6 * GSTRIDE + 2]);
        apply_gateY<3>(r, Gk[5 * GSTRIDE], Gk[5 * GSTRIDE + 1], Gk[5 * GSTRIDE + 2]);
        apply_gateY<4>(r, Gk[4 * GSTRIDE], Gk[4 * GSTRIDE + 1], Gk[4 * GSTRIDE + 2]);
        {
            const int hi = (tid >> 5) << 10, lo = tid & 31;
#pragma unroll
            for (int j = 0; j < 32; j++) sv[hi + (j << 5) + (lo ^ j)] = r[j];
        }
        __syncthreads();   // B-store -> C-load crosses warps

        // ===== Pass C: i = (j<<9)|tid, wires 0..3 (j bits 4..1) =====
        {
            const int mid = (tid >> 5) & 15;
#pragma unroll
            for (int j = 0; j < 32; j++) {
                int sl = (j << 9) | (tid ^ mid ^ ((j & 1) << 4));
                r[j] = sv[sl];
            }
        }
        apply_gateY<4>(r, Gk[0 * GSTRIDE], Gk[0 * GSTRIDE + 1], Gk[0 * GSTRIDE + 2]);
        apply_gateY<3>(r, Gk[1 * GSTRIDE], Gk[1 * GSTRIDE + 1], Gk[1 * GSTRIDE + 2]);
        apply_gateY<2>(r, Gk[2 * GSTRIDE], Gk[2 * GSTRIDE + 1], Gk[2 * GSTRIDE + 2]);
        apply_gateY<1>(r, Gk[3 * GSTRIDE], Gk[3 * GSTRIDE + 1], Gk[3 * GSTRIDE + 2]);

        if (k < NL - 1) {
            // D_L (all 14 wires): pass-C layout.
            // hi: tid bit m <-> i bit m <-> wire (13-m), factor zL.
            float2 ptL = make_float2(1.f, 0.f);
#pragma unroll
            for (int m = 0; m < 9; m++) {
                if ((tid >> m) & 1) {
                    const u64* g = Gk + (13 - m) * GSTRIDE;
                    float zr, zd, zi, zt;
                    unpk(g[5], zr, zd); unpk(g[6], zt, zi);
                    ptL = cmul(ptL, make_float2(zr, zi));
                }
            }
            const u64 BtL = pk(ptL.x, ptL.x), PtL = pk(-ptL.y, ptL.y);
#pragma unroll
            for (int j = 0; j < 32; j++)
                r[j] = dphase(dphase(r[j], sTLB[k * 32 + j], sTLP[k * 32 + j]), BtL, PtL);
            // CNOT-chain permutation fused into the store.
#pragma unroll
            for (int j = 0; j < 32; j++) {
                unsigned i = (unsigned)((j << 9) | tid);
                sv[sw((int)cnot_perm(i))] = r[j];
            }
            __syncthreads();
        } else {
            // Last layer: D_L is a pure phase -> |amp|^2 unaffected, skip it.
            // <Z0>: sign = permuted bit13 = parity(src bits 0..12).
            float acc = 0.f;
#pragma unroll
            for (int j = 0; j < 32; j++) {
                int i = (j << 9) | tid;
                float re, im; unpk(r[j], re, im);
                float vv = fmaf(re, re, im * im);
                acc += (__popc(i & 0x1FFF) & 1) ? -vv : vv;
            }
#pragma unroll
            for (int off = 16; off; off >>= 1)
                acc += __shfl_xor_sync(0xffffffffu, acc, off);
            if ((tid & 31) == 0) sred[tid >> 5] = acc;
            __syncthreads();
            if (tid < 32) {
                float v = (tid < 16) ? sred[tid] : 0.f;
#pragma unroll
                for (int off = 8; off; off >>= 1)
                    v += __shfl_xor_sync(0xffffffffu, v, off);
                if (tid == 0) out[b] = v;
            }
        }
    }
}

extern "C" void kernel_launch(void* const* d_in, const int* in_sizes, int n_in,
                              void* d_out, int out_size) {
    const float* x   = (const float*)d_in[0];
    const float* ang = (const float*)d_in[1];
    if (n_in >= 2 && in_sizes[0] == NL * NW * 3 && in_sizes[1] != NL * NW * 3) {
        const float* t = x; x = ang; ang = t;
    }
    float* out = (float*)d_out;

    const int smem_bytes = (NSTATE + NL * NW * GSTRIDE + 4 * NL * 32) * 8
                         + NW * 8 + 16 * 4;
    cudaFuncSetAttribute(vqc_kernel, cudaFuncAttributeMaxDynamicSharedMemorySize,
                         smem_bytes);
    vqc_kernel<<<1024, THREADS, smem_bytes>>>(x, ang, out);
}

// round 7
// speedup vs baseline: 1.8794x; 1.0417x over previous
#include <cuda_runtime.h>
#include <math.h>

#define NW 14
#define NL 4
#define NSTATE (1 << NW)
#define THREADS 512
#define PI_F 3.14159265358979323846f

typedef unsigned long long u64;

// ---------- packed f32x2 helpers ----------
__device__ __forceinline__ u64 pk(float lo, float hi) {
    u64 r; asm("mov.b64 %0, {%1, %2};" : "=l"(r) : "f"(lo), "f"(hi)); return r;
}
__device__ __forceinline__ void unpk(u64 a, float& lo, float& hi) {
    asm("mov.b64 {%0, %1}, %2;" : "=f"(lo), "=f"(hi) : "l"(a));
}
__device__ __forceinline__ u64 swp(u64 a) {
    float lo, hi; unpk(a, lo, hi);
    u64 r; asm("mov.b64 %0, {%1, %2};" : "=l"(r) : "f"(hi), "f"(lo)); return r;
}
__device__ __forceinline__ u64 ffma2_(u64 a, u64 b, u64 c) {
    u64 d; asm("fma.rn.f32x2 %0, %1, %2, %3;" : "=l"(d) : "l"(a), "l"(b), "l"(c));
    return d;
}
__device__ __forceinline__ u64 fmul2_(u64 a, u64 b) {
    u64 d; asm("mul.rn.f32x2 %0, %1, %2;" : "=l"(d) : "l"(a), "l"(b));
    return d;
}

__device__ __forceinline__ float2 cmul(float2 a, float2 b) {
    return make_float2(a.x * b.x - a.y * b.y, a.x * b.y + a.y * b.x);
}
__device__ __forceinline__ float2 cadd(float2 a, float2 b) {
    return make_float2(a.x + b.x, a.y + b.y);
}

// Real RY butterfly on local bit L: y0 = c*x0 - s*x1, y1 = s*x0 + c*x1.
template <int L>
__device__ __forceinline__ void apply_gateY(u64* r, u64 C2, u64 Sp, u64 Sn) {
#pragma unroll
    for (int p = 0; p < 16; p++) {
        const int lm = (1 << L) - 1;
        const int j0 = ((p & ~lm) << 1) | (p & lm);
        const int j1 = j0 | (1 << L);
        u64 x0 = r[j0], x1 = r[j1];
        r[j0] = ffma2_(Sn, x1, fmul2_(C2, x0));
        r[j1] = ffma2_(Sp, x0, fmul2_(C2, x1));
    }
}

// Per-amp phase multiply: y = z*x, z as B=(zr,zr), P=(-zi,+zi).
__device__ __forceinline__ u64 dphase(u64 x, u64 B, u64 P) {
    return ffma2_(B, x, fmul2_(P, swp(x)));
}

// CNOT chain as basis permutation: dst_k = xor(src k..13) (k<=12),
// dst_13 = xor(src 0..12).
__device__ __forceinline__ unsigned cnot_perm(unsigned i) {
    unsigned s = i;
    s ^= s >> 1; s ^= s >> 2; s ^= s >> 4; s ^= s >> 8;
    return (s & 0x1FFFu) | (((s ^ (i >> 13)) & 1u) << 13);
}

// Scatter swizzle (pass-A layout): slot(i) = i ^ ((i>>5)&31).
__device__ __forceinline__ int sw(int i) { return i ^ ((i >> 5) & 31); }

__global__ __launch_bounds__(THREADS, 1)
void vqc_kernel(const float* __restrict__ x_raw,
                const float* __restrict__ angles,
                float* __restrict__ out) {
    extern __shared__ unsigned char smem[];
    u64*    sv   = (u64*)smem;                 // [NSTATE]
    u64*    sU   = sv + NSTATE;                // [NL*NW*3]  C2,Sp,Sn
    u64*    sTB  = sU + NL * NW * 3;           // [3*32] boundary diag table B
    u64*    sTP  = sTB + 3 * 32;               // [3*32] boundary diag table P
    float2* sT0  = (float2*)(sTP + 3 * 32);    // [32]  layer-0 D_R j-table
    float2* senc = sT0 + 32;                   // [NW]
    float2* sSb  = senc + NW;                  // [3]  e^{i sum(beta 5..13)}
    float2* sZ13 = sSb + 3;                    // [3]  e^{i beta(wire0)}
    float*  sAL  = (float*)(sZ13 + 3);         // [NL*NW] ZYZ alpha
    float*  sBE  = sAL + NL * NW;              // [NL*NW] ZYZ beta
    float*  sred = sBE + NL * NW;              // [16]

    const int tid = threadIdx.x;
    const int b   = blockIdx.x;

    // suffix-xor of tid (9 bits): bit m = xor(tid_m..tid_8)
    int stx = tid;
    stx ^= stx >> 1; stx ^= stx >> 2; stx ^= stx >> 4; stx ^= stx >> 8;

    // ---- phase 1: encoding factors + ZYZ decomposition ----
    if (tid < NW) {
        float t = tanhf(x_raw[b * NW + tid]) * PI_F;
        senc[tid] = make_float2(cosf(0.5f * t), sinf(0.5f * t));
    }
    if (tid < NL * NW) {
        const int k = tid / NW, w = tid % NW;
        const float a0 = angles[(k * NW + w) * 3 + 0];
        const float a1 = angles[(k * NW + w) * 3 + 1];
        const float a2 = angles[(k * NW + w) * 3 + 2];
        const float c0 = cosf(0.5f * a0), s0 = sinf(0.5f * a0);
        const float c1 = cosf(0.5f * a1), s1 = sinf(0.5f * a1);
        const float2 rx00 = make_float2(c0, 0.f),  rx01 = make_float2(0.f, -s0);
        const float2 rx10 = make_float2(0.f, -s0), rx11 = make_float2(c0, 0.f);
        const float2 ry00 = make_float2(c1, 0.f),  ry01 = make_float2(-s1, 0.f);
        const float2 ry10 = make_float2(s1, 0.f),  ry11 = make_float2(c1, 0.f);
        float2 m00 = cadd(cmul(ry00, rx00), cmul(ry01, rx10));
        float2 m10 = cadd(cmul(ry10, rx00), cmul(ry11, rx10));
        const float2 em = make_float2(cosf(0.5f * a2), -sinf(0.5f * a2));
        const float2 ep = make_float2(em.x, -em.y);
        float2 u00 = cmul(em, m00);
        float2 u10 = cmul(ep, m10);
        // ZYZ: u00 = c*e^{-i(al+be)/2}, u10 = s*e^{i(al-be)/2}
        float c  = sqrtf(u00.x * u00.x + u00.y * u00.y);
        float s  = sqrtf(u10.x * u10.x + u10.y * u10.y);
        float pp = -atan2f(u00.y, u00.x);
        float pm =  atan2f(u10.y, u10.x);
        float al = pp + pm, be = pp - pm;
        sU[tid * 3 + 0] = pk(c, c);
        sU[tid * 3 + 1] = pk(s, s);
        sU[tid * 3 + 2] = pk(-s, -s);
        sAL[tid] = al;
        sBE[tid] = be;
    }
    __syncthreads();

    // ---- phase 2: diagonal tables ----
    if (tid < 32) {
        // layer-0 D_R over j (pass-A layout: j bit b = wire 13-b)
        float a = 0.f;
#pragma unroll
        for (int bb = 0; bb < 5; bb++)
            if ((tid >> bb) & 1) a += sBE[13 - bb];
        sT0[tid] = make_float2(cosf(a), sinf(a));
    } else if (tid < 128) {
        // boundary bk j-tables (pass-C layout: j bit q = i bit 9+q = wire 4-q)
        const int bk = (tid - 32) >> 5, j = tid & 31;
        int sj = j; sj ^= sj >> 1; sj ^= sj >> 2; sj ^= sj >> 4; // suffix xor 5b
        float a = 0.f;
#pragma unroll
        for (int q = 0; q < 5; q++)
            if ((j >> q) & 1) a += sAL[bk * NW + 4 - q];        // D_L of layer bk
#pragma unroll
        for (int q = 0; q < 4; q++)                              // dst bits 9..12
            if ((sj >> q) & 1) a += sBE[(bk + 1) * NW + 4 - q]; // D_R of next
        sTB[bk * 32 + j] = pk(cosf(a), cosf(a));
        sTP[bk * 32 + j] = pk(-sinf(a), sinf(a));
    } else if (tid < 131) {
        const int bk = tid - 128;
        float sb = 0.f;
#pragma unroll
        for (int m = 0; m < 9; m++) sb += sBE[(bk + 1) * NW + 13 - m];
        sSb[bk] = make_float2(cosf(sb), sinf(sb));
        float c13 = sBE[(bk + 1) * NW + 0];       // wire 0 -> dst bit 13
        sZ13[bk] = make_float2(cosf(c13), sinf(c13));
    }
    __syncthreads();

    u64 r[32];

    for (int k = 0; k < NL; k++) {
        const u64* Gk = sU + k * NW * 3;

        // ===== Pass A: i = tid*32 + j, wires 9..13 (j bits 4..0) =====
        if (k == 0) {
            float v[32];
            float common = 1.f;
#pragma unroll
            for (int w = 0; w < 9; w++) {
                float2 cs = senc[w];
                common *= ((tid >> (8 - w)) & 1) ? cs.y : cs.x;
            }
            v[0] = common;
#pragma unroll
            for (int st = 0; st < 5; st++) {
                float2 cs = senc[9 + st];
#pragma unroll
                for (int kk = (1 << st) - 1; kk >= 0; kk--) {
                    float t = v[kk];
                    v[2 * kk + 1] = t * cs.y;
                    v[2 * kk]     = t * cs.x;
                }
            }
            // layer-0 D_R thread phase (i bit 5+m = wire 8-m)
            float th0 = 0.f;
#pragma unroll
            for (int m = 0; m < 9; m++)
                if ((tid >> m) & 1) th0 += sBE[8 - m];
            float s0t, c0t; __sincosf(th0, &s0t, &c0t);
            const float2 z0 = make_float2(c0t, s0t);
#pragma unroll
            for (int j = 0; j < 32; j++) {
                float2 zj = cmul(z0, sT0[j]);
                r[j] = pk(v[j] * zj.x, v[j] * zj.y);
            }
        } else {
            const int m = tid & 31, base = tid * 32;
#pragma unroll
            for (int j = 0; j < 32; j++) r[j] = sv[base + (j ^ m)];
        }
        apply_gateY<0>(r, Gk[13 * 3], Gk[13 * 3 + 1], Gk[13 * 3 + 2]);
        apply_gateY<1>(r, Gk[12 * 3], Gk[12 * 3 + 1], Gk[12 * 3 + 2]);
        apply_gateY<2>(r, Gk[11 * 3], Gk[11 * 3 + 1], Gk[11 * 3 + 2]);
        apply_gateY<3>(r, Gk[10 * 3], Gk[10 * 3 + 1], Gk[10 * 3 + 2]);
        apply_gateY<4>(r, Gk[ 9 * 3], Gk[ 9 * 3 + 1], Gk[ 9 * 3 + 2]);
        {
            const int m = tid & 31, base = tid * 32;
#pragma unroll
            for (int j = 0; j < 32; j++) sv[base + (j ^ m)] = r[j];
        }
        __syncwarp();   // A-store -> B-load is warp-private

        // ===== Pass B: i = ((tid>>5)<<10)|(j<<5)|(tid&31), wires 4..8 =====
        {
            const int hi = (tid >> 5) << 10, lo = tid & 31;
#pragma unroll
            for (int j = 0; j < 32; j++) r[j] = sv[hi + (j << 5) + (lo ^ j)];
        }
        apply_gateY<0>(r, Gk[8 * 3], Gk[8 * 3 + 1], Gk[8 * 3 + 2]);
        apply_gateY<1>(r, Gk[7 * 3], Gk[7 * 3 + 1], Gk[7 * 3 + 2]);
        apply_gateY<2>(r, Gk[6 * 3], Gk[6 * 3 + 1], Gk[6 * 3 + 2]);
        apply_gateY<3>(r, Gk[5 * 3], Gk[5 * 3 + 1], Gk[5 * 3 + 2]);
        apply_gateY<4>(r, Gk[4 * 3], Gk[4 * 3 + 1], Gk[4 * 3 + 2]);
        {
            const int hi = (tid >> 5) << 10, lo = tid & 31;
#pragma unroll
            for (int j = 0; j < 32; j++) sv[hi + (j << 5) + (lo ^ j)] = r[j];
        }
        __syncthreads();   // B-store -> C-load crosses warps

        // ===== Pass C: i = (j<<9)|tid, wires 0..3 (local bits 4..1) =====
        {
            const int mid = (tid >> 5) & 15;
#pragma unroll
            for (int j = 0; j < 32; j++) {
                int sl = (j << 9) | (tid ^ mid ^ ((j & 1) << 4));
                r[j] = sv[sl];
            }
        }
        apply_gateY<4>(r, Gk[0 * 3], Gk[0 * 3 + 1], Gk[0 * 3 + 2]);
        apply_gateY<3>(r, Gk[1 * 3], Gk[1 * 3 + 1], Gk[1 * 3 + 2]);
        apply_gateY<2>(r, Gk[2 * 3], Gk[2 * 3 + 1], Gk[2 * 3 + 2]);
        apply_gateY<1>(r, Gk[3 * 3], Gk[3 * 3 + 1], Gk[3 * 3 + 2]);

        if (k < NL - 1) {
            // ---- combined diagonal D_R(k+1) o P o D_L(k), applied pre-scatter.
            // phi(i) = [j-table] + W[t][t'] where t=par(j0..4), t'=par(j0..3):
            //   thread part: thA = sum alpha_k(wire 13-m) tid_m   (D_L, bits 0-8)
            //                thB = sum beta_{k+1}(wire 13-m) stx_m (D_R, dst 0-8)
            //   t flips all stx terms; t' toggles dst-bit-13 term c13 with
            //   thread parity p = stx_0.
            float thA = 0.f, thB = 0.f;
#pragma unroll
            for (int m = 0; m < 9; m++) {
                if ((tid >> m) & 1) thA += sAL[k * NW + 13 - m];
                if ((stx >> m) & 1) thB += sBE[(k + 1) * NW + 13 - m];
            }
            float sa, ca, sb2, cb2;
            __sincosf(thA, &sa, &ca);
            __sincosf(thB, &sb2, &cb2);
            const float2 zA = make_float2(ca, sa);
            const float2 zB = make_float2(cb2, sb2);
            float2 A0 = cmul(zA, zB);
            float2 A1 = cmul(cmul(zA, make_float2(cb2, -sb2)), sSb[k]);
            const float2 z13 = sZ13[k];
            float2 A0x = cmul(A0, z13), A1x = cmul(A1, z13);
            float2 V00, V01, V10, V11;   // V[t][t']
            if (stx & 1) { V00 = A0x; V01 = A0;  V10 = A1x; V11 = A1;  }
            else         { V00 = A0;  V01 = A0x; V10 = A1;  V11 = A1x; }
            const u64 B00 = pk(V00.x, V00.x), P00 = pk(-V00.y, V00.y);
            const u64 B01 = pk(V01.x, V01.x), P01 = pk(-V01.y, V01.y);
            const u64 B10 = pk(V10.x, V10.x), P10 = pk(-V10.y, V10.y);
            const u64 B11 = pk(V11.x, V11.x), P11 = pk(-V11.y, V11.y);
            const u64* TBk = sTB + k * 32;
            const u64* TPk = sTP + k * 32;
#pragma unroll
            for (int j = 0; j < 32; j++) {
                const int t  = __popc(j) & 1;        // compile-time
                const int tp = __popc(j & 15) & 1;   // compile-time
                const u64 WB = t ? (tp ? B11 : B10) : (tp ? B01 : B00);
                const u64 WP = t ? (tp ? P11 : P10) : (tp ? P01 : P00);
                r[j] = dphase(dphase(r[j], TBk[j], TPk[j]), WB, WP);
            }
            // CNOT-chain permutation fused into the store.
#pragma unroll
            for (int j = 0; j < 32; j++) {
                unsigned i = (unsigned)((j << 9) | tid);
                sv[sw((int)cnot_perm(i))] = r[j];
            }
            __syncthreads();
        } else {
            // Last layer: trailing phases drop under |amp|^2.
            // <Z0>: sign = permuted bit13 = parity(src bits 0..12).
            float acc = 0.f;
#pragma unroll
            for (int j = 0; j < 32; j++) {
                int i = (j << 9) | tid;
                float re, im; unpk(r[j], re, im);
                float vv = fmaf(re, re, im * im);
                acc += (__popc(i & 0x1FFF) & 1) ? -vv : vv;
            }
#pragma unroll
            for (int off = 16; off; off >>= 1)
                acc += __shfl_xor_sync(0xffffffffu, acc, off);
            if ((tid & 31) == 0) sred[tid >> 5] = acc;
            __syncthreads();
            if (tid < 32) {
                float v = (tid < 16) ? sred[tid] : 0.f;
#pragma unroll
                for (int off = 8; off; off >>= 1)
                    v += __shfl_xor_sync(0xffffffffu, v, off);
                if (tid == 0) out[b] = v;
            }
        }
    }
}

extern "C" void kernel_launch(void* const* d_in, const int* in_sizes, int n_in,
                              void* d_out, int out_size) {
    const float* x   = (const float*)d_in[0];
    const float* ang = (const float*)d_in[1];
    if (n_in >= 2 && in_sizes[0] == NL * NW * 3 && in_sizes[1] != NL * NW * 3) {
        const float* t = x; x = ang; ang = t;
    }
    float* out = (float*)d_out;

    const int smem_bytes =
        (NSTATE + NL * NW * 3 + 2 * 3 * 32) * 8      // sv, sU, sTB, sTP
        + (32 + NW + 3 + 3) * 8                      // sT0, senc, sSb, sZ13
        + (2 * NL * NW + 16) * 4;                    // sAL, sBE, sred
    cudaFuncSetAttribute(vqc_kernel, cudaFuncAttributeMaxDynamicSharedMemorySize,
                         smem_bytes);
    vqc_kernel<<<1024, THREADS, smem_bytes>>>(x, ang, out);
}

// round 8
// speedup vs baseline: 2.1784x; 1.1591x over previous
#include <cuda_runtime.h>
#include <math.h>

#define NW 14
#define NL 4
#define NSTATE (1 << NW)
#define THREADS 512
#define PI_F 3.14159265358979323846f

typedef unsigned long long u64;

// ---------- packed f32x2 helpers ----------
__device__ __forceinline__ u64 pk(float lo, float hi) {
    u64 r; asm("mov.b64 %0, {%1, %2};" : "=l"(r) : "f"(lo), "f"(hi)); return r;
}
__device__ __forceinline__ void unpk(u64 a, float& lo, float& hi) {
    asm("mov.b64 {%0, %1}, %2;" : "=f"(lo), "=f"(hi) : "l"(a));
}
__device__ __forceinline__ u64 swp(u64 a) {
    float lo, hi; unpk(a, lo, hi);
    u64 r; asm("mov.b64 %0, {%1, %2};" : "=l"(r) : "f"(hi), "f"(lo)); return r;
}
__device__ __forceinline__ u64 ffma2_(u64 a, u64 b, u64 c) {
    u64 d; asm("fma.rn.f32x2 %0, %1, %2, %3;" : "=l"(d) : "l"(a), "l"(b), "l"(c));
    return d;
}
__device__ __forceinline__ u64 fmul2_(u64 a, u64 b) {
    u64 d; asm("mul.rn.f32x2 %0, %1, %2;" : "=l"(d) : "l"(a), "l"(b));
    return d;
}

__device__ __forceinline__ float2 cmul(float2 a, float2 b) {
    return make_float2(a.x * b.x - a.y * b.y, a.x * b.y + a.y * b.x);
}

// Tangent-form RY butterfly on local bit L:
//   y0 = x0 - t*x1, y1 = x1 + t*x0   (uniform cos factor deferred to the end)
template <int L>
__device__ __forceinline__ void apply_gateT(u64* r, u64 Tp, u64 Tn) {
#pragma unroll
    for (int p = 0; p < 16; p++) {
        const int lm = (1 << L) - 1;
        const int j0 = ((p & ~lm) << 1) | (p & lm);
        const int j1 = j0 | (1 << L);
        u64 x0 = r[j0], x1 = r[j1];
        r[j0] = ffma2_(Tn, x1, x0);
        r[j1] = ffma2_(Tp, x0, x1);
    }
}

// Per-amp phase multiply: y = z*x, z as B=(zr,zr), P=(-zi,+zi).
__device__ __forceinline__ u64 dphase(u64 x, u64 B, u64 P) {
    return ffma2_(B, x, fmul2_(P, swp(x)));
}

// CNOT chain as basis permutation: dst_k = xor(src k..13) (k<=12),
// dst_13 = xor(src 0..12).
__device__ __forceinline__ unsigned cnot_perm(unsigned i) {
    unsigned s = i;
    s ^= s >> 1; s ^= s >> 2; s ^= s >> 4; s ^= s >> 8;
    return (s & 0x1FFFu) | (((s ^ (i >> 13)) & 1u) << 13);
}

// Scatter swizzle (pass-A layout): slot(i) = i ^ ((i>>5)&31).
__device__ __forceinline__ int sw(int i) { return i ^ ((i >> 5) & 31); }

__global__ __launch_bounds__(THREADS, 1)
void vqc_kernel(const float* __restrict__ x_raw,
                const float* __restrict__ angles,
                float* __restrict__ out) {
    extern __shared__ unsigned char smem[];
    u64*    sv   = (u64*)smem;                 // [NSTATE]
    u64*    sU   = sv + NSTATE;                // [NL*NW*2]  Tp,Tn
    u64*    sTB  = sU + NL * NW * 2;           // [3*32] boundary diag table B
    u64*    sTP  = sTB + 3 * 32;               // [3*32] boundary diag table P
    float2* sT0  = (float2*)(sTP + 3 * 32);    // [32]  layer-0 D_R j-table
    float2* senc = sT0 + 32;                   // [NW]
    float2* sSb  = senc + NW;                  // [3]  e^{i sum(beta 5..13)}
    float2* sZ13 = sSb + 3;                    // [3]  e^{i beta(wire0)}
    float*  sAL  = (float*)(sZ13 + 3);         // [NL*NW] ZYZ alpha
    float*  sBE  = sAL + NL * NW;              // [NL*NW] ZYZ beta
    float*  sC   = sBE + NL * NW;              // [NL*NW] ZYZ cos
    float*  sS2  = sC + NL * NW;               // [1] total scale^2
    float*  sred = sS2 + 1;                    // [16]

    const int tid = threadIdx.x;
    const int b   = blockIdx.x;

    // suffix-xor of tid (9 bits): bit m = xor(tid_m..tid_8)
    int stx = tid;
    stx ^= stx >> 1; stx ^= stx >> 2; stx ^= stx >> 4; stx ^= stx >> 8;

    // ---- phase 1: encoding factors + ZYZ decomposition ----
    if (tid < NW) {
        float t = tanhf(x_raw[b * NW + tid]) * PI_F;
        senc[tid] = make_float2(cosf(0.5f * t), sinf(0.5f * t));
    }
    if (tid < NL * NW) {
        const int k = tid / NW, w = tid % NW;
        const float a0 = angles[(k * NW + w) * 3 + 0];
        const float a1 = angles[(k * NW + w) * 3 + 1];
        const float a2 = angles[(k * NW + w) * 3 + 2];
        const float c0 = cosf(0.5f * a0), s0 = sinf(0.5f * a0);
        const float c1 = cosf(0.5f * a1), s1 = sinf(0.5f * a1);
        // m00, m10 of RY(a1)*RX(a0)
        float2 m00 = make_float2(c1 * c0, s1 * s0);    // c1*c0 + (-s1)*(-i s0)*...:
        // (recompute explicitly to avoid sign slips)
        {
            const float2 ry00 = make_float2(c1, 0.f), ry01 = make_float2(-s1, 0.f);
            const float2 rx00 = make_float2(c0, 0.f), rx10 = make_float2(0.f, -s0);
            m00 = make_float2(ry00.x * rx00.x - ry00.y * rx00.y
                              + ry01.x * rx10.x - ry01.y * rx10.y,
                              ry00.x * rx00.y + ry00.y * rx00.x
                              + ry01.x * rx10.y + ry01.y * rx10.x);
        }
        float2 m10;
        {
            const float2 ry10 = make_float2(s1, 0.f), ry11 = make_float2(c1, 0.f);
            const float2 rx00 = make_float2(c0, 0.f), rx10 = make_float2(0.f, -s0);
            m10 = make_float2(ry10.x * rx00.x - ry10.y * rx00.y
                              + ry11.x * rx10.x - ry11.y * rx10.y,
                              ry10.x * rx00.y + ry10.y * rx00.x
                              + ry11.x * rx10.y + ry11.y * rx10.x);
        }
        const float2 em = make_float2(cosf(0.5f * a2), -sinf(0.5f * a2));
        const float2 ep = make_float2(em.x, -em.y);
        float2 u00 = cmul(em, m00);
        float2 u10 = cmul(ep, m10);
        // ZYZ: u00 = c*e^{-i(al+be)/2}, u10 = s*e^{i(al-be)/2}
        float c  = sqrtf(u00.x * u00.x + u00.y * u00.y);
        float s  = sqrtf(u10.x * u10.x + u10.y * u10.y);
        float pp = -atan2f(u00.y, u00.x);
        float pm =  atan2f(u10.y, u10.x);
        float al = pp + pm, be = pp - pm;
        float t  = s / c;                 // safe: variational angles are small
        sU[tid * 2 + 0] = pk(t, t);
        sU[tid * 2 + 1] = pk(-t, -t);
        sAL[tid] = al;
        sBE[tid] = be;
        sC[tid]  = c;
    }
    __syncthreads();

    // ---- phase 2: diagonal tables + global scale ----
    if (tid < 32) {
        // layer-0 D_R over j (pass-A layout: j bit b = wire 13-b)
        float a = 0.f;
#pragma unroll
        for (int bb = 0; bb < 5; bb++)
            if ((tid >> bb) & 1) a += sBE[13 - bb];
        sT0[tid] = make_float2(cosf(a), sinf(a));
    } else if (tid < 128) {
        // boundary bk j-tables (pass-C layout: j bit q = i bit 9+q = wire 4-q)
        const int bk = (tid - 32) >> 5, j = tid & 31;
        int sj = j; sj ^= sj >> 1; sj ^= sj >> 2; sj ^= sj >> 4;
        float a = 0.f;
#pragma unroll
        for (int q = 0; q < 5; q++)
            if ((j >> q) & 1) a += sAL[bk * NW + 4 - q];
#pragma unroll
        for (int q = 0; q < 4; q++)
            if ((sj >> q) & 1) a += sBE[(bk + 1) * NW + 4 - q];
        sTB[bk * 32 + j] = pk(cosf(a), cosf(a));
        sTP[bk * 32 + j] = pk(-sinf(a), sinf(a));
    } else if (tid < 131) {
        const int bk = tid - 128;
        float sb = 0.f;
#pragma unroll
        for (int m = 0; m < 9; m++) sb += sBE[(bk + 1) * NW + 13 - m];
        sSb[bk] = make_float2(cosf(sb), sinf(sb));
        float c13 = sBE[(bk + 1) * NW + 0];
        sZ13[bk] = make_float2(cosf(c13), sinf(c13));
    } else if (tid == 131) {
        float S = 1.f;
#pragma unroll
        for (int i = 0; i < NL * NW; i++) S *= sC[i];
        sS2[0] = S * S;
    }
    __syncthreads();

    u64 r[32];

    for (int k = 0; k < NL; k++) {
        const u64* Gk = sU + k * NW * 2;

        // ===== Pass A: i = tid*32 + j, wires 9..13 (j bits 4..0) =====
        if (k == 0) {
            float v[32];
            float common = 1.f;
#pragma unroll
            for (int w = 0; w < 9; w++) {
                float2 cs = senc[w];
                common *= ((tid >> (8 - w)) & 1) ? cs.y : cs.x;
            }
            v[0] = common;
#pragma unroll
            for (int st = 0; st < 5; st++) {
                float2 cs = senc[9 + st];
#pragma unroll
                for (int kk = (1 << st) - 1; kk >= 0; kk--) {
                    float t = v[kk];
                    v[2 * kk + 1] = t * cs.y;
                    v[2 * kk]     = t * cs.x;
                }
            }
            float th0 = 0.f;
#pragma unroll
            for (int m = 0; m < 9; m++)
                if ((tid >> m) & 1) th0 += sBE[8 - m];
            float s0t, c0t; __sincosf(th0, &s0t, &c0t);
            const float2 z0 = make_float2(c0t, s0t);
#pragma unroll
            for (int j = 0; j < 32; j++) {
                float2 zj = cmul(z0, sT0[j]);
                r[j] = pk(v[j] * zj.x, v[j] * zj.y);
            }
        } else {
            const int m = tid & 31, base = tid * 32;
#pragma unroll
            for (int j = 0; j < 32; j++) r[j] = sv[base + (j ^ m)];
        }
        apply_gateT<0>(r, Gk[13 * 2], Gk[13 * 2 + 1]);
        apply_gateT<1>(r, Gk[12 * 2], Gk[12 * 2 + 1]);
        apply_gateT<2>(r, Gk[11 * 2], Gk[11 * 2 + 1]);
        apply_gateT<3>(r, Gk[10 * 2], Gk[10 * 2 + 1]);
        apply_gateT<4>(r, Gk[ 9 * 2], Gk[ 9 * 2 + 1]);
        {
            const int m = tid & 31, base = tid * 32;
#pragma unroll
            for (int j = 0; j < 32; j++) sv[base + (j ^ m)] = r[j];
        }
        __syncwarp();   // A-store -> B-load is warp-private

        // ===== Pass B: i = ((tid>>5)<<10)|(j<<5)|(tid&31), wires 4..8 =====
        {
            const int hi = (tid >> 5) << 10, lo = tid & 31;
#pragma unroll
            for (int j = 0; j < 32; j++) r[j] = sv[hi + (j << 5) + (lo ^ j)];
        }
        apply_gateT<0>(r, Gk[8 * 2], Gk[8 * 2 + 1]);
        apply_gateT<1>(r, Gk[7 * 2], Gk[7 * 2 + 1]);
        apply_gateT<2>(r, Gk[6 * 2], Gk[6 * 2 + 1]);
        apply_gateT<3>(r, Gk[5 * 2], Gk[5 * 2 + 1]);
        apply_gateT<4>(r, Gk[4 * 2], Gk[4 * 2 + 1]);
        {
            const int hi = (tid >> 5) << 10, lo = tid & 31;
#pragma unroll
            for (int j = 0; j < 32; j++) sv[hi + (j << 5) + (lo ^ j)] = r[j];
        }
        __syncthreads();   // B-store -> C-load crosses warps

        // ===== Pass C: i = (j<<9)|tid, wires 0..3 (local bits 4..1) =====
        {
            const int mid = (tid >> 5) & 15;
#pragma unroll
            for (int j = 0; j < 32; j++) {
                int sl = (j << 9) | (tid ^ mid ^ ((j & 1) << 4));
                r[j] = sv[sl];
            }
        }
        apply_gateT<4>(r, Gk[0 * 2], Gk[0 * 2 + 1]);
        apply_gateT<3>(r, Gk[1 * 2], Gk[1 * 2 + 1]);
        apply_gateT<2>(r, Gk[2 * 2], Gk[2 * 2 + 1]);
        apply_gateT<1>(r, Gk[3 * 2], Gk[3 * 2 + 1]);

        if (k < NL - 1) {
            // combined diagonal D_R(k+1) o P o D_L(k), applied pre-scatter.
            float thA = 0.f, thB = 0.f;
#pragma unroll
            for (int m = 0; m < 9; m++) {
                if ((tid >> m) & 1) thA += sAL[k * NW + 13 - m];
                if ((stx >> m) & 1) thB += sBE[(k + 1) * NW + 13 - m];
            }
            float sa, ca, sb2, cb2;
            __sincosf(thA, &sa, &ca);
            __sincosf(thB, &sb2, &cb2);
            const float2 zA = make_float2(ca, sa);
            const float2 zB = make_float2(cb2, sb2);
            float2 A0 = cmul(zA, zB);
            float2 A1 = cmul(cmul(zA, make_float2(cb2, -sb2)), sSb[k]);
            const float2 z13 = sZ13[k];
            float2 A0x = cmul(A0, z13), A1x = cmul(A1, z13);
            float2 V00, V01, V10, V11;   // V[t][t']
            if (stx & 1) { V00 = A0x; V01 = A0;  V10 = A1x; V11 = A1;  }
            else         { V00 = A0;  V01 = A0x; V10 = A1;  V11 = A1x; }
            const u64 B00 = pk(V00.x, V00.x), P00 = pk(-V00.y, V00.y);
            const u64 B01 = pk(V01.x, V01.x), P01 = pk(-V01.y, V01.y);
            const u64 B10 = pk(V10.x, V10.x), P10 = pk(-V10.y, V10.y);
            const u64 B11 = pk(V11.x, V11.x), P11 = pk(-V11.y, V11.y);
            const u64* TBk = sTB + k * 32;
            const u64* TPk = sTP + k * 32;
#pragma unroll
            for (int j = 0; j < 32; j++) {
                const int t  = __popc(j) & 1;
                const int tp = __popc(j & 15) & 1;
                const u64 WB = t ? (tp ? B11 : B10) : (tp ? B01 : B00);
                const u64 WP = t ? (tp ? P11 : P10) : (tp ? P01 : P00);
                r[j] = dphase(dphase(r[j], TBk[j], TPk[j]), WB, WP);
            }
            // CNOT-chain permutation fused into the store.
#pragma unroll
            for (int j = 0; j < 32; j++) {
                unsigned i = (unsigned)((j << 9) | tid);
                sv[sw((int)cnot_perm(i))] = r[j];
            }
            __syncthreads();
        } else {
            // <Z0>: sign = permuted bit13 = parity(src bits 0..12);
            // global tangent-form scale applied at the end.
            float acc = 0.f;
#pragma unroll
            for (int j = 0; j < 32; j++) {
                int i = (j << 9) | tid;
                float re, im; unpk(r[j], re, im);
                float vv = fmaf(re, re, im * im);
                acc += (__popc(i & 0x1FFF) & 1) ? -vv : vv;
            }
#pragma unroll
            for (int off = 16; off; off >>= 1)
                acc += __shfl_xor_sync(0xffffffffu, acc, off);
            if ((tid & 31) == 0) sred[tid >> 5] = acc;
            __syncthreads();
            if (tid < 32) {
                float v = (tid < 16) ? sred[tid] : 0.f;
#pragma unroll
                for (int off = 8; off; off >>= 1)
                    v += __shfl_xor_sync(0xffffffffu, v, off);
                if (tid == 0) out[b] = v * sS2[0];
            }
        }
    }
}

extern "C" void kernel_launch(void* const* d_in, const int* in_sizes, int n_in,
                              void* d_out, int out_size) {
    const float* x   = (const float*)d_in[0];
    const float* ang = (const float*)d_in[1];
    if (n_in >= 2 && in_sizes[0] == NL * NW * 3 && in_sizes[1] != NL * NW * 3) {
        const float* t = x; x = ang; ang = t;
    }
    float* out = (float*)d_out;

    const int smem_bytes =
        (NSTATE + NL * NW * 2 + 2 * 3 * 32) * 8      // sv, sU, sTB, sTP
        + (32 + NW + 3 + 3) * 8                      // sT0, senc, sSb, sZ13
        + (3 * NL * NW + 1 + 16) * 4;                // sAL, sBE, sC, sS2, sred
    cudaFuncSetAttribute(vqc_kernel, cudaFuncAttributeMaxDynamicSharedMemorySize,
                         smem_bytes);
    vqc_kernel<<<1024, THREADS, smem_bytes>>>(x, ang, out);
}

// round 10
// speedup vs baseline: 2.5288x; 1.1609x over previous
#include <cuda_runtime.h>
#include <math.h>

#define NW 14
#define NL 4
#define NSTATE (1 << NW)
#define THREADS 512
#define PI_F 3.14159265358979323846f

typedef unsigned long long u64;

// ---------- packed f32x2 helpers ----------
__device__ __forceinline__ u64 pk(float lo, float hi) {
    u64 r; asm("mov.b64 %0, {%1, %2};" : "=l"(r) : "f"(lo), "f"(hi)); return r;
}
__device__ __forceinline__ void unpk(u64 a, float& lo, float& hi) {
    asm("mov.b64 {%0, %1}, %2;" : "=f"(lo), "=f"(hi) : "l"(a));
}
__device__ __forceinline__ u64 swp(u64 a) {
    float lo, hi; unpk(a, lo, hi);
    u64 r; asm("mov.b64 %0, {%1, %2};" : "=l"(r) : "f"(hi), "f"(lo)); return r;
}
__device__ __forceinline__ u64 ffma2_(u64 a, u64 b, u64 c) {
    u64 d; asm("fma.rn.f32x2 %0, %1, %2, %3;" : "=l"(d) : "l"(a), "l"(b), "l"(c));
    return d;
}
__device__ __forceinline__ u64 fmul2_(u64 a, u64 b) {
    u64 d; asm("mul.rn.f32x2 %0, %1, %2;" : "=l"(d) : "l"(a), "l"(b));
    return d;
}

__device__ __forceinline__ float2 cmul(float2 a, float2 b) {
    return make_float2(a.x * b.x - a.y * b.y, a.x * b.y + a.y * b.x);
}

// Tangent-form RY butterfly on local bit L of a full 32-amp block.
template <int L>
__device__ __forceinline__ void apply_gateT(u64* r, u64 Tp, u64 Tn) {
#pragma unroll
    for (int p = 0; p < 16; p++) {
        const int lm = (1 << L) - 1;
        const int j0 = ((p & ~lm) << 1) | (p & lm);
        const int j1 = j0 | (1 << L);
        u64 x0 = r[j0], x1 = r[j1];
        r[j0] = ffma2_(Tn, x1, x0);
        r[j1] = ffma2_(Tp, x0, x1);
    }
}

// Tangent-form RY butterfly on local bit L (0..3) of a 16-amp half-block.
template <int L>
__device__ __forceinline__ void apply_gateT_h(u64* h, u64 Tp, u64 Tn) {
#pragma unroll
    for (int p = 0; p < 8; p++) {
        const int lm = (1 << L) - 1;
        const int j0 = ((p & ~lm) << 1) | (p & lm);
        const int j1 = j0 | (1 << L);
        u64 x0 = h[j0], x1 = h[j1];
        h[j0] = ffma2_(Tn, x1, x0);
        h[j1] = ffma2_(Tp, x0, x1);
    }
}

// Per-amp phase multiply: y = z*x, z as B=(zr,zr), P=(-zi,+zi).
__device__ __forceinline__ u64 dphase(u64 x, u64 B, u64 P) {
    return ffma2_(B, x, fmul2_(P, swp(x)));
}

// CNOT chain as GF(2)-linear basis permutation.
__device__ __forceinline__ unsigned cnot_perm(unsigned i) {
    unsigned s = i;
    s ^= s >> 1; s ^= s >> 2; s ^= s >> 4; s ^= s >> 8;
    return (s & 0x1FFFu) | (((s ^ (i >> 13)) & 1u) << 13);
}

// Scatter swizzle (pass-A layout): slot(i) = i ^ ((i>>5)&31). GF(2)-linear.
__device__ __forceinline__ int sw(int i) { return i ^ ((i >> 5) & 31); }

__global__ __launch_bounds__(THREADS, 1)
void vqc_kernel(const float* __restrict__ x_raw,
                const float* __restrict__ angles,
                float* __restrict__ out) {
    extern __shared__ unsigned char smem[];
    u64*    sv   = (u64*)smem;                 // [NSTATE]
    u64*    sU   = sv + NSTATE;                // [NL*NW*2]  Tp,Tn
    u64*    sTB  = sU + NL * NW * 2;           // [3*32] boundary diag table B
    u64*    sTP  = sTB + 3 * 32;               // [3*32] boundary diag table P
    float2* sT0  = (float2*)(sTP + 3 * 32);    // [32]  layer-0 D_R j-table
    float2* senc = sT0 + 32;                   // [NW]
    float2* sSb  = senc + NW;                  // [3]  e^{i sum(beta 5..13)}
    float2* sZ13 = sSb + 3;                    // [3]  e^{i beta(wire0)}
    float*  sAL  = (float*)(sZ13 + 3);         // [NL*NW] ZYZ alpha
    float*  sBE  = sAL + NL * NW;              // [NL*NW] ZYZ beta
    float*  sC   = sBE + NL * NW;              // [NL*NW] ZYZ cos
    float*  sS2  = sC + NL * NW;               // [1] total scale^2
    float*  sred = sS2 + 1;                    // [16]

    const int tid = threadIdx.x;
    const int b   = blockIdx.x;

    // suffix-xor of tid (9 bits)
    int stx = tid;
    stx ^= stx >> 1; stx ^= stx >> 2; stx ^= stx >> 4; stx ^= stx >> 8;
    // per-thread GF(2)-linear parts: scatter slot offset + reduction sign
    const int pts     = sw((int)cnot_perm((unsigned)tid));
    const int sgn_tid = __popc(tid) & 1;

    // ---- phase 1: encoding factors + ZYZ decomposition ----
    if (tid < NW) {
        float t = tanhf(x_raw[b * NW + tid]) * PI_F;
        senc[tid] = make_float2(cosf(0.5f * t), sinf(0.5f * t));
    }
    if (tid < NL * NW) {
        const int k = tid / NW, w = tid % NW;
        const float a0 = angles[(k * NW + w) * 3 + 0];
        const float a1 = angles[(k * NW + w) * 3 + 1];
        const float a2 = angles[(k * NW + w) * 3 + 2];
        const float c0 = cosf(0.5f * a0), s0 = sinf(0.5f * a0);
        const float c1 = cosf(0.5f * a1), s1 = sinf(0.5f * a1);
        float2 m00, m10;
        {
            const float2 ry00 = make_float2(c1, 0.f), ry01 = make_float2(-s1, 0.f);
            const float2 rx00 = make_float2(c0, 0.f), rx10 = make_float2(0.f, -s0);
            m00 = make_float2(ry00.x * rx00.x - ry00.y * rx00.y
                              + ry01.x * rx10.x - ry01.y * rx10.y,
                              ry00.x * rx00.y + ry00.y * rx00.x
                              + ry01.x * rx10.y + ry01.y * rx10.x);
            const float2 ry10 = make_float2(s1, 0.f), ry11 = make_float2(c1, 0.f);
            m10 = make_float2(ry10.x * rx00.x - ry10.y * rx00.y
                              + ry11.x * rx10.x - ry11.y * rx10.y,
                              ry10.x * rx00.y + ry10.y * rx00.x
                              + ry11.x * rx10.y + ry11.y * rx10.x);
        }
        const float2 em = make_float2(cosf(0.5f * a2), -sinf(0.5f * a2));
        const float2 ep = make_float2(em.x, -em.y);
        float2 u00 = cmul(em, m00);
        float2 u10 = cmul(ep, m10);
        float c  = sqrtf(u00.x * u00.x + u00.y * u00.y);
        float s  = sqrtf(u10.x * u10.x + u10.y * u10.y);
        float pp = -atan2f(u00.y, u00.x);
        float pm =  atan2f(u10.y, u10.x);
        float al = pp + pm, be = pp - pm;
        float t  = s / c;
        sU[tid * 2 + 0] = pk(t, t);
        sU[tid * 2 + 1] = pk(-t, -t);
        sAL[tid] = al;
        sBE[tid] = be;
        sC[tid]  = c;
    }
    __syncthreads();

    // ---- phase 2: diagonal tables + global scale ----
    if (tid < 32) {
        float a = 0.f;
#pragma unroll
        for (int bb = 0; bb < 5; bb++)
            if ((tid >> bb) & 1) a += sBE[13 - bb];
        sT0[tid] = make_float2(cosf(a), sinf(a));
    } else if (tid < 128) {
        const int bk = (tid - 32) >> 5, j = tid & 31;
        int sj = j; sj ^= sj >> 1; sj ^= sj >> 2; sj ^= sj >> 4;
        float a = 0.f;
#pragma unroll
        for (int q = 0; q < 5; q++)
            if ((j >> q) & 1) a += sAL[bk * NW + 4 - q];
#pragma unroll
        for (int q = 0; q < 4; q++)
            if ((sj >> q) & 1) a += sBE[(bk + 1) * NW + 4 - q];
        sTB[bk * 32 + j] = pk(cosf(a), cosf(a));
        sTP[bk * 32 + j] = pk(-sinf(a), sinf(a));
    } else if (tid < 131) {
        const int bk = tid - 128;
        float sb = 0.f;
#pragma unroll
        for (int m = 0; m < 9; m++) sb += sBE[(bk + 1) * NW + 13 - m];
        sSb[bk] = make_float2(cosf(sb), sinf(sb));
        float c13 = sBE[(bk + 1) * NW + 0];
        sZ13[bk] = make_float2(cosf(c13), sinf(c13));
    } else if (tid == 131) {
        float S = 1.f;
#pragma unroll
        for (int i = 0; i < NL * NW; i++) S *= sC[i];
        sS2[0] = S * S;
    }
    __syncthreads();

    u64 r[32];

    for (int k = 0; k < NL; k++) {
        const u64* Gk = sU + k * NW * 2;

        // ===== Pass A: i = tid*32 + j, wires 9..13 (j bits 4..0) =====
        if (k == 0) {
            float v[32];
            float common = 1.f;
#pragma unroll
            for (int w = 0; w < 9; w++) {
                float2 cs = senc[w];
                common *= ((tid >> (8 - w)) & 1) ? cs.y : cs.x;
            }
            v[0] = common;
#pragma unroll
            for (int st = 0; st < 5; st++) {
                float2 cs = senc[9 + st];
#pragma unroll
                for (int kk = (1 << st) - 1; kk >= 0; kk--) {
                    float t = v[kk];
                    v[2 * kk + 1] = t * cs.y;
                    v[2 * kk]     = t * cs.x;
                }
            }
            float th0 = 0.f;
#pragma unroll
            for (int m = 0; m < 9; m++)
                if ((tid >> m) & 1) th0 += sBE[8 - m];
            float s0t, c0t; __sincosf(th0, &s0t, &c0t);
            const float2 z0 = make_float2(c0t, s0t);
#pragma unroll
            for (int j = 0; j < 32; j++) {
                float2 zj = cmul(z0, sT0[j]);
                r[j] = pk(v[j] * zj.x, v[j] * zj.y);
            }
            apply_gateT<0>(r, Gk[13 * 2], Gk[13 * 2 + 1]);
            apply_gateT<1>(r, Gk[12 * 2], Gk[12 * 2 + 1]);
            apply_gateT<2>(r, Gk[11 * 2], Gk[11 * 2 + 1]);
            apply_gateT<3>(r, Gk[10 * 2], Gk[10 * 2 + 1]);
        } else {
            const int m = tid & 31, base = tid * 32;
            // pipelined: halves load, then half-gates
#pragma unroll
            for (int j = 0; j < 16; j++) r[j] = sv[base + (j ^ m)];
#pragma unroll
            for (int j = 16; j < 32; j++) r[j] = sv[base + (j ^ m)];
            apply_gateT_h<0>(r,      Gk[13 * 2], Gk[13 * 2 + 1]);
            apply_gateT_h<1>(r,      Gk[12 * 2], Gk[12 * 2 + 1]);
            apply_gateT_h<2>(r,      Gk[11 * 2], Gk[11 * 2 + 1]);
            apply_gateT_h<3>(r,      Gk[10 * 2], Gk[10 * 2 + 1]);
            apply_gateT_h<0>(r + 16, Gk[13 * 2], Gk[13 * 2 + 1]);
            apply_gateT_h<1>(r + 16, Gk[12 * 2], Gk[12 * 2 + 1]);
            apply_gateT_h<2>(r + 16, Gk[11 * 2], Gk[11 * 2 + 1]);
            apply_gateT_h<3>(r + 16, Gk[10 * 2], Gk[10 * 2 + 1]);
        }
        apply_gateT<4>(r, Gk[9 * 2], Gk[9 * 2 + 1]);
        {
            const int m = tid & 31, base = tid * 32;
#pragma unroll
            for (int j = 0; j < 32; j++) sv[base + (j ^ m)] = r[j];
        }
        __syncwarp();   // A-store -> B-load is warp-private

        // ===== Pass B: i = ((tid>>5)<<10)|(j<<5)|(tid&31), wires 4..8 =====
        // (B region is also warp-private: bits 5..9 of slot = lane-derived,
        //  bits 10..13 = warp id bits)
        {
            const int hi = (tid >> 5) << 10, lo = tid & 31;
#pragma unroll
            for (int j = 0; j < 16; j++) r[j] = sv[hi + (j << 5) + (lo ^ j)];
#pragma unroll
            for (int j = 16; j < 32; j++) r[j] = sv[hi + (j << 5) + (lo ^ j)];
            apply_gateT_h<0>(r,      Gk[8 * 2], Gk[8 * 2 + 1]);
            apply_gateT_h<1>(r,      Gk[7 * 2], Gk[7 * 2 + 1]);
            apply_gateT_h<2>(r,      Gk[6 * 2], Gk[6 * 2 + 1]);
            apply_gateT_h<3>(r,      Gk[5 * 2], Gk[5 * 2 + 1]);
            apply_gateT_h<0>(r + 16, Gk[8 * 2], Gk[8 * 2 + 1]);
            apply_gateT_h<1>(r + 16, Gk[7 * 2], Gk[7 * 2 + 1]);
            apply_gateT_h<2>(r + 16, Gk[6 * 2], Gk[6 * 2 + 1]);
            apply_gateT_h<3>(r + 16, Gk[5 * 2], Gk[5 * 2 + 1]);
            apply_gateT<4>(r, Gk[4 * 2], Gk[4 * 2 + 1]);
#pragma unroll
            for (int j = 0; j < 32; j++) sv[hi + (j << 5) + (lo ^ j)] = r[j];
        }
        __syncthreads();   // B-store -> C-load crosses warps

        // ===== Pass C: i = (j<<9)|tid, wires 0..3 on j bits 1..4; j bit 0 inert.
        if (k < NL - 1) {
            // V constants first (MUFU latency hides under C loads)
            float thA = 0.f, thB = 0.f;
#pragma unroll
            for (int m = 0; m < 9; m++) {
                if ((tid >> m) & 1) thA += sAL[k * NW + 13 - m];
                if ((stx >> m) & 1) thB += sBE[(k + 1) * NW + 13 - m];
            }
            float sa, ca, sb2, cb2;
            __sincosf(thA, &sa, &ca);
            __sincosf(thB, &sb2, &cb2);
            const float2 zA = make_float2(ca, sa);
            float2 A0 = cmul(zA, make_float2(cb2, sb2));
            float2 A1 = cmul(cmul(zA, make_float2(cb2, -sb2)), sSb[k]);
            const float2 z13 = sZ13[k];
            float2 A0x = cmul(A0, z13), A1x = cmul(A1, z13);
            float2 V00, V01, V10, V11;   // V[t][t']
            if (stx & 1) { V00 = A0x; V01 = A0;  V10 = A1x; V11 = A1;  }
            else         { V00 = A0;  V01 = A0x; V10 = A1;  V11 = A1x; }
            const u64 B00 = pk(V00.x, V00.x), P00 = pk(-V00.y, V00.y);
            const u64 B01 = pk(V01.x, V01.x), P01 = pk(-V01.y, V01.y);
            const u64 B10 = pk(V10.x, V10.x), P10 = pk(-V10.y, V10.y);
            const u64 B11 = pk(V11.x, V11.x), P11 = pk(-V11.y, V11.y);
            const u64* TBk = sTB + k * 32;
            const u64* TPk = sTP + k * 32;
            const int mid = (tid >> 5) & 15;

            u64* re = r;          // even-j stream
            u64* ro = r + 16;     // odd-j stream
#pragma unroll
            for (int q = 0; q < 16; q++)
                re[q] = sv[((2 * q) << 9) | (tid ^ mid)];
#pragma unroll
            for (int q = 0; q < 16; q++)
                ro[q] = sv[((2 * q + 1) << 9) | (tid ^ mid ^ 16)];
            // gates + diag, all in registers
            apply_gateT_h<0>(re, Gk[3 * 2], Gk[3 * 2 + 1]);
            apply_gateT_h<1>(re, Gk[2 * 2], Gk[2 * 2 + 1]);
            apply_gateT_h<2>(re, Gk[1 * 2], Gk[1 * 2 + 1]);
            apply_gateT_h<3>(re, Gk[0 * 2], Gk[0 * 2 + 1]);
            apply_gateT_h<0>(ro, Gk[3 * 2], Gk[3 * 2 + 1]);
            apply_gateT_h<1>(ro, Gk[2 * 2], Gk[2 * 2 + 1]);
            apply_gateT_h<2>(ro, Gk[1 * 2], Gk[1 * 2 + 1]);
            apply_gateT_h<3>(ro, Gk[0 * 2], Gk[0 * 2 + 1]);
#pragma unroll
            for (int q = 0; q < 32; q++) {
                const int j  = (q & 15) * 2 + (q >> 4);
                const int t  = __popc(j) & 1;
                const int tp = __popc(j & 15) & 1;
                const u64 WB = t ? (tp ? B11 : B10) : (tp ? B01 : B00);
                const u64 WP = t ? (tp ? P11 : P10) : (tp ? P01 : P00);
                r[q] = dphase(dphase(r[q], TBk[j], TPk[j]), WB, WP);
            }
            // All C-loads CTA-wide must complete before ANY scatter store:
            // the scatter crosses warp regions (this barrier fixes the latent
            // race present since R1; R9 exposed it).
            __syncthreads();
#pragma unroll
            for (int q = 0; q < 32; q++) {
                const int j = (q & 15) * 2 + (q >> 4);
                sv[sw((int)cnot_perm((unsigned)(j << 9))) ^ pts] = r[q];
            }
            __syncthreads();   // scatter -> next-layer A-load crosses warps
        } else {
            const int mid = (tid >> 5) & 15;
            u64* re = r;
            u64* ro = r + 16;
#pragma unroll
            for (int q = 0; q < 16; q++)
                re[q] = sv[((2 * q) << 9) | (tid ^ mid)];
#pragma unroll
            for (int q = 0; q < 16; q++)
                ro[q] = sv[((2 * q + 1) << 9) | (tid ^ mid ^ 16)];
            apply_gateT_h<0>(re, Gk[3 * 2], Gk[3 * 2 + 1]);
            apply_gateT_h<1>(re, Gk[2 * 2], Gk[2 * 2 + 1]);
            apply_gateT_h<2>(re, Gk[1 * 2], Gk[1 * 2 + 1]);
            apply_gateT_h<3>(re, Gk[0 * 2], Gk[0 * 2 + 1]);
            apply_gateT_h<0>(ro, Gk[3 * 2], Gk[3 * 2 + 1]);
            apply_gateT_h<1>(ro, Gk[2 * 2], Gk[2 * 2 + 1]);
            apply_gateT_h<2>(ro, Gk[1 * 2], Gk[1 * 2 + 1]);
            apply_gateT_h<3>(ro, Gk[0 * 2], Gk[0 * 2 + 1]);
            // <Z0>: per-j sign = parity(j&15) (compile-time), thread sign once.
            float acc = 0.f;
#pragma unroll
            for (int q = 0; q < 16; q++) {
                const int j = 2 * q;
                float re1, im1; unpk(re[q], re1, im1);
                float v1 = fmaf(re1, re1, im1 * im1);
                acc += (__popc(j & 15) & 1) ? -v1 : v1;
                const int j2 = 2 * q + 1;
                float re2, im2; unpk(ro[q], re2, im2);
                float v2 = fmaf(re2, re2, im2 * im2);
                acc += (__popc(j2 & 15) & 1) ? -v2 : v2;
            }
            acc = sgn_tid ? -acc : acc;
#pragma unroll
            for (int off = 16; off; off >>= 1)
                acc += __shfl_xor_sync(0xffffffffu, acc, off);
            if ((tid & 31) == 0) sred[tid >> 5] = acc;
            __syncthreads();
            if (tid < 32) {
                float v = (tid < 16) ? sred[tid] : 0.f;
#pragma unroll
                for (int off = 8; off; off >>= 1)
                    v += __shfl_xor_sync(0xffffffffu, v, off);
                if (tid == 0) out[b] = v * sS2[0];
            }
        }
    }
}

extern "C" void kernel_launch(void* const* d_in, const int* in_sizes, int n_in,
                              void* d_out, int out_size) {
    const float* x   = (const float*)d_in[0];
    const float* ang = (const float*)d_in[1];
    if (n_in >= 2 && in_sizes[0] == NL * NW * 3 && in_sizes[1] != NL * NW * 3) {
        const float* t = x; x = ang; ang = t;
    }
    float* out = (float*)d_out;

    const int smem_bytes =
        (NSTATE + NL * NW * 2 + 2 * 3 * 32) * 8
        + (32 + NW + 3 + 3) * 8
        + (3 * NL * NW + 1 + 16) * 4;
    cudaFuncSetAttribute(vqc_kernel, cudaFuncAttributeMaxDynamicSharedMemorySize,
                         smem_bytes);
    vqc_kernel<<<1024, THREADS, smem_bytes>>>(x, ang, out);
}